// round 1
// baseline (speedup 1.0000x reference)
#include <cuda_runtime.h>
#include <cstdint>

#define CIN 512
#define SEQ 1024
#define NH 16
#define HD 64

// ---------------- scratch (device globals: allowed; no allocs) ----------------
__device__ float g_Q[2 * SEQ * NH * HD];          // [b][s][h][d]   8 MB
__device__ float g_K[2 * SEQ * NH * HD];          // [b][s][h][d]   8 MB
__device__ float g_V[2 * NH * SEQ * HD];          // [b][h][k][d]   8 MB
__device__ float g_J[(size_t)2 * NH * SEQ * SEQ]; // [b][h][q][k] 128 MB
__device__ float g_U[(size_t)2 * NH * SEQ * SEQ]; // [b][v][q][k] 128 MB
__device__ float g_O[2 * SEQ * NH * HD];          // [b][q][v*64+d] 8 MB

// ---------------- fast exp on the FMA pipe (no MUFU) ----------------
__device__ __forceinline__ float fast_exp(float x) {
    // exp(x) = 2^(x*log2e); valid for |x| < ~80, rel err ~3e-6
    float t  = fmaf(x, 1.4426950408889634f, 12582912.0f); // round-to-int trick
    float fi = t - 12582912.0f;
    float f  = fmaf(x, 1.4426950408889634f, -fi);         // frac in [-0.5, 0.5]
    int   n  = __float_as_int(t) - 0x4B400000;            // integer part
    float p  = 1.33335581e-3f;
    p = fmaf(p, f, 9.61812911e-3f);
    p = fmaf(p, f, 5.55041087e-2f);
    p = fmaf(p, f, 2.40226507e-1f);
    p = fmaf(p, f, 6.93147181e-1f);
    p = fmaf(p, f, 1.0f);
    return p * __int_as_float((n + 127) << 23);
}

// ================= K1: fused QKV projection =================
// C[s, j] = sum_c inp[b][c][s] * W[c][j],  j in [0,3072) selects Wq/Wk/Wv
__global__ void k1_proj(const float* __restrict__ inp,
                        const float* __restrict__ Wq, const float* __restrict__ Wk,
                        const float* __restrict__ Wv,
                        const float* __restrict__ aq, const float* __restrict__ ak,
                        const float* __restrict__ av) {
    __shared__ float As[16][64];
    __shared__ float Bs[16][64];
    int b  = blockIdx.z;
    int n0 = blockIdx.x * 64;   // j
    int m0 = blockIdx.y * 64;   // s
    int jm  = n0 >> 10;
    int jn0 = n0 & 1023;
    const float* W = (jm == 0) ? Wq : ((jm == 1) ? Wk : Wv);
    float al = (jm == 0) ? aq[0] : ((jm == 1) ? ak[0] : av[0]);
    float scale = 1.0f / (1.0f + fast_exp(-al));

    int tid = threadIdx.x;
    int tx = tid & 15, ty = tid >> 4;
    int cc = tid >> 4;            // row for staging loads (16 rows)
    int col4 = (tid & 15) * 4;    // col*4 (64 cols)
    const float* inpb = inp + b * CIN * SEQ;

    float acc[4][4] = {};
    for (int c0 = 0; c0 < CIN; c0 += 16) {
        *(float4*)&As[cc][col4] = *(const float4*)&inpb[(c0 + cc) * SEQ + m0 + col4];
        *(float4*)&Bs[cc][col4] = *(const float4*)&W[(c0 + cc) * 1024 + jn0 + col4];
        __syncthreads();
#pragma unroll
        for (int kk = 0; kk < 16; kk++) {
            float4 a  = *(float4*)&As[kk][ty * 4];
            float4 bb = *(float4*)&Bs[kk][tx * 4];
            float av4[4] = {a.x, a.y, a.z, a.w};
            float bv4[4] = {bb.x, bb.y, bb.z, bb.w};
#pragma unroll
            for (int i = 0; i < 4; i++)
#pragma unroll
                for (int j = 0; j < 4; j++)
                    acc[i][j] = fmaf(av4[i], bv4[j], acc[i][j]);
        }
        __syncthreads();
    }
#pragma unroll
    for (int i = 0; i < 4; i++) {
        int s = m0 + ty * 4 + i;
#pragma unroll
        for (int j = 0; j < 4; j++) {
            int jj = jn0 + tx * 4 + j;
            int d = jj >> 4, h = jj & 15;
            float v = acc[i][j] * scale;
            if (jm == 0)      g_Q[b * 1048576 + s * 1024 + h * 64 + d] = v;
            else if (jm == 1) g_K[b * 1048576 + s * 1024 + h * 64 + d] = v;
            else              g_V[b * 1048576 + h * 65536 + s * 64 + d] = v;
        }
    }
}

// ================= K2: J[b,h,q,k] = sum_d Q[q,h,d] * K[k,h,d] =================
__global__ void k2_J() {
    __shared__ float As[16][68];
    __shared__ float Bs[16][68];
    int bh = blockIdx.z;
    int b = bh >> 4, h = bh & 15;
    int k0 = blockIdx.x * 64, q0 = blockIdx.y * 64;
    const float* Qb = g_Q + b * 1048576 + h * 64;
    const float* Kb = g_K + b * 1048576 + h * 64;

    int tid = threadIdx.x;
    int tx = tid & 15, ty = tid >> 4;
    int rr  = tid >> 2;          // 0..63
    int dd4 = (tid & 3) * 4;     // 0,4,8,12

    float acc[4][4] = {};
    for (int d0 = 0; d0 < 64; d0 += 16) {
        float4 a = *(const float4*)&Qb[(q0 + rr) * 1024 + d0 + dd4];
        As[dd4][rr] = a.x; As[dd4 + 1][rr] = a.y; As[dd4 + 2][rr] = a.z; As[dd4 + 3][rr] = a.w;
        float4 bb = *(const float4*)&Kb[(k0 + rr) * 1024 + d0 + dd4];
        Bs[dd4][rr] = bb.x; Bs[dd4 + 1][rr] = bb.y; Bs[dd4 + 2][rr] = bb.z; Bs[dd4 + 3][rr] = bb.w;
        __syncthreads();
#pragma unroll
        for (int kk = 0; kk < 16; kk++) {
            float4 a4 = *(float4*)&As[kk][ty * 4];
            float4 b4 = *(float4*)&Bs[kk][tx * 4];
            float avv[4] = {a4.x, a4.y, a4.z, a4.w};
            float bvv[4] = {b4.x, b4.y, b4.z, b4.w};
#pragma unroll
            for (int i = 0; i < 4; i++)
#pragma unroll
                for (int j = 0; j < 4; j++)
                    acc[i][j] = fmaf(avv[i], bvv[j], acc[i][j]);
        }
        __syncthreads();
    }
    float* Jp = g_J + ((size_t)bh << 20);
#pragma unroll
    for (int i = 0; i < 4; i++) {
        int q = q0 + ty * 4 + i;
        float4 o = make_float4(acc[i][0], acc[i][1], acc[i][2], acc[i][3]);
        *(float4*)&Jp[(size_t)q * 1024 + k0 + tx * 4] = o;
    }
}

// ====== K34: per (b,q): EL = J@Wl - mask, softmax over k, U = W@Ww ======
__global__ void k34_softmax_U(const float* __restrict__ mask,
                              const float* __restrict__ Wl,
                              const float* __restrict__ Ww) {
    extern __shared__ float sE[];       // [1024][17] padded exp cache (~68KB)
    __shared__ float sWl[256];
    __shared__ float sWw[256];
    __shared__ float red[8][16];
    __shared__ float sInv[16];

    int q = blockIdx.x, b = blockIdx.y;
    int tid = threadIdx.x;
    sWl[tid] = Wl[tid & 255];
    sWw[tid] = Ww[tid & 255];
    __syncthreads();

    const float* Jb = g_J + (size_t)b * 16777216 + (size_t)q * 1024;
    float psum[16] = {};

    for (int k = tid; k < 1024; k += 256) {
        float j[16];
#pragma unroll
        for (int h = 0; h < 16; h++) j[h] = Jb[(size_t)h * 1048576 + k];
        float mk = mask[b * 1024 + k];
#pragma unroll
        for (int g = 0; g < 16; g++) {
            float el = -mk;
#pragma unroll
            for (int h = 0; h < 16; h++) el = fmaf(j[h], sWl[h * 16 + g], el);
            float e = fast_exp(el);
            sE[k * 17 + g] = e;
            psum[g] += e;
        }
    }
    // deterministic reduction: warp shfl -> smem -> final 16 lanes
#pragma unroll
    for (int g = 0; g < 16; g++) {
        float v = psum[g];
#pragma unroll
        for (int off = 16; off > 0; off >>= 1)
            v += __shfl_down_sync(0xffffffff, v, off);
        if ((tid & 31) == 0) red[tid >> 5][g] = v;
    }
    __syncthreads();
    if (tid < 16) {
        float t = 0.f;
#pragma unroll
        for (int w = 0; w < 8; w++) t += red[w][tid];
        sInv[tid] = 1.0f / t;
    }
    __syncthreads();

    float* Ub = g_U + (size_t)b * 16777216 + (size_t)q * 1024;
    for (int k = tid; k < 1024; k += 256) {
        float e[16];
#pragma unroll
        for (int g = 0; g < 16; g++) e[g] = sE[k * 17 + g] * sInv[g];
#pragma unroll
        for (int v = 0; v < 16; v++) {
            float u = 0.f;
#pragma unroll
            for (int g = 0; g < 16; g++) u = fmaf(e[g], sWw[g * 16 + v], u);
            Ub[(size_t)v * 1048576 + k] = u;
        }
    }
}

// ================= K5: O[b,q,v*64+d] = sum_k U[b,v,q,k] * V[b,v,k,d] =================
__global__ void k5_O() {
    __shared__ float As[16][68];
    __shared__ float Bs[16][64];
    int bv = blockIdx.z;
    int b = bv >> 4, v = bv & 15;
    int q0 = blockIdx.y * 64;
    const float* U = g_U + ((size_t)bv << 20);
    const float* Vp = g_V + b * 1048576 + v * 65536;

    int tid = threadIdx.x;
    int tx = tid & 15, ty = tid >> 4;
    int rr = tid >> 2, kk4 = (tid & 3) * 4;
    int cc = tid >> 4, col4 = (tid & 15) * 4;

    float acc[4][4] = {};
    for (int k0 = 0; k0 < 1024; k0 += 16) {
        float4 a = *(const float4*)&U[(size_t)(q0 + rr) * 1024 + k0 + kk4];
        As[kk4][rr] = a.x; As[kk4 + 1][rr] = a.y; As[kk4 + 2][rr] = a.z; As[kk4 + 3][rr] = a.w;
        *(float4*)&Bs[cc][col4] = *(const float4*)&Vp[(k0 + cc) * 64 + col4];
        __syncthreads();
#pragma unroll
        for (int kk = 0; kk < 16; kk++) {
            float4 a4 = *(float4*)&As[kk][ty * 4];
            float4 b4 = *(float4*)&Bs[kk][tx * 4];
            float avv[4] = {a4.x, a4.y, a4.z, a4.w};
            float bvv[4] = {b4.x, b4.y, b4.z, b4.w};
#pragma unroll
            for (int i = 0; i < 4; i++)
#pragma unroll
                for (int j = 0; j < 4; j++)
                    acc[i][j] = fmaf(avv[i], bvv[j], acc[i][j]);
        }
        __syncthreads();
    }
#pragma unroll
    for (int i = 0; i < 4; i++) {
        int qq = q0 + ty * 4 + i;
        float4 o = make_float4(acc[i][0], acc[i][1], acc[i][2], acc[i][3]);
        *(float4*)&g_O[b * 1048576 + qq * 1024 + v * 64 + tx * 4] = o;
    }
}

// ================= K6: out[b,c,q] = inp[b,c,q] + sum_j O[b,q,j'] * Wo[perm(j'),c] ====
__global__ void k6_out(const float* __restrict__ inp, const float* __restrict__ Wo,
                       float* __restrict__ out) {
    __shared__ float As[16][68];
    __shared__ float Bs[16][64];
    __shared__ float Cs[64][65];
    int b = blockIdx.z;
    int c0 = blockIdx.x * 64, q0 = blockIdx.y * 64;
    const float* O = g_O + b * 1048576;

    int tid = threadIdx.x;
    int tx = tid & 15, ty = tid >> 4;
    int rr = tid >> 2, jj4 = (tid & 3) * 4;
    int brow = tid >> 4, bcol4 = (tid & 15) * 4;

    float acc[4][4] = {};
    for (int j0 = 0; j0 < 1024; j0 += 16) {
        float4 a = *(const float4*)&O[(q0 + rr) * 1024 + j0 + jj4];
        As[jj4][rr] = a.x; As[jj4 + 1][rr] = a.y; As[jj4 + 2][rr] = a.z; As[jj4 + 3][rr] = a.w;
        int jj = j0 + brow;                       // stored index j' = v*64+d
        int wrow = ((jj & 63) << 4) | (jj >> 6);  // real j = d*16+v
        *(float4*)&Bs[brow][bcol4] = *(const float4*)&Wo[wrow * 512 + c0 + bcol4];
        __syncthreads();
#pragma unroll
        for (int kk = 0; kk < 16; kk++) {
            float4 a4 = *(float4*)&As[kk][ty * 4];
            float4 b4 = *(float4*)&Bs[kk][tx * 4];
            float avv[4] = {a4.x, a4.y, a4.z, a4.w};
            float bvv[4] = {b4.x, b4.y, b4.z, b4.w};
#pragma unroll
            for (int i = 0; i < 4; i++)
#pragma unroll
                for (int j = 0; j < 4; j++)
                    acc[i][j] = fmaf(avv[i], bvv[j], acc[i][j]);
        }
        __syncthreads();
    }
    // transpose through smem so the (c,q)-layout store is q-coalesced
#pragma unroll
    for (int i = 0; i < 4; i++)
#pragma unroll
        for (int j = 0; j < 4; j++)
            Cs[tx * 4 + j][ty * 4 + i] = acc[i][j];
    __syncthreads();
#pragma unroll
    for (int t = 0; t < 16; t++) {
        int idx = tid + t * 256;
        int ccc = idx >> 6, qq = idx & 63;
        size_t off = (size_t)b * 524288 + (size_t)(c0 + ccc) * 1024 + (q0 + qq);
        out[off] = inp[off] + Cs[ccc][qq];
    }
}

// ================= launch =================
extern "C" void kernel_launch(void* const* d_in, const int* in_sizes, int n_in,
                              void* d_out, int out_size) {
    const float* inp  = (const float*)d_in[0];
    const float* mask = (const float*)d_in[1];
    const float* Wq   = (const float*)d_in[2];
    const float* Wk   = (const float*)d_in[3];
    const float* Wv   = (const float*)d_in[4];
    const float* aq   = (const float*)d_in[5];
    const float* ak   = (const float*)d_in[6];
    const float* av   = (const float*)d_in[7];
    const float* Wl   = (const float*)d_in[8];
    const float* Ww   = (const float*)d_in[9];
    const float* Wo   = (const float*)d_in[10];
    float* out = (float*)d_out;

    const int SMEM_K34 = 1024 * 17 * 4; // 69632 B
    cudaFuncSetAttribute(k34_softmax_U, cudaFuncAttributeMaxDynamicSharedMemorySize, SMEM_K34);

    k1_proj<<<dim3(48, 16, 2), 256>>>(inp, Wq, Wk, Wv, aq, ak, av);
    k2_J<<<dim3(16, 16, 32), 256>>>();
    k34_softmax_U<<<dim3(1024, 2), 256, SMEM_K34>>>(mask, Wl, Ww);
    k5_O<<<dim3(1, 16, 32), 256>>>();
    k6_out<<<dim3(8, 16, 2), 256>>>(inp, Wo, out);
}

// round 2
// speedup vs baseline: 1.0210x; 1.0210x over previous
#include <cuda_runtime.h>
#include <cstdint>

#define CIN 512
#define SEQ 1024

// ---------------- scratch ----------------
__device__ float g_Q[2 * 1024 * 1024];            // [b][s][h*64+d]
__device__ float g_K[2 * 1024 * 1024];            // [b][s][h*64+d]
__device__ float g_V[2 * 1024 * 1024];            // [b][h][k][d]
__device__ float g_J[(size_t)2 * 16 * 1024 * 1024]; // [b][h][q][k]
__device__ float g_U[(size_t)2 * 16 * 1024 * 1024]; // [b][v][q][k]
__device__ float g_O[2 * 1024 * 1024];            // [b][q][v*64+d]
__device__ float g_P[4 * 512 * 1024];             // split-K partials for k6

// ---------------- fast exp on the FMA pipe ----------------
__device__ __forceinline__ float fast_exp(float x) {
    float t  = fmaf(x, 1.4426950408889634f, 12582912.0f);
    float fi = t - 12582912.0f;
    float f  = fmaf(x, 1.4426950408889634f, -fi);
    int   n  = __float_as_int(t) - 0x4B400000;
    float p  = 1.33335581e-3f;
    p = fmaf(p, f, 9.61812911e-3f);
    p = fmaf(p, f, 5.55041087e-2f);
    p = fmaf(p, f, 2.40226507e-1f);
    p = fmaf(p, f, 6.93147181e-1f);
    p = fmaf(p, f, 1.0f);
    return p * __int_as_float((n + 127) << 23);
}

#define BPERM(n) (((((n) & 15)) << 3) | ((n) >> 4))

// ================= K1: fused QKV projection (128x128x8 DB, 8x8 micro) =================
__global__ __launch_bounds__(256) void k1_proj(const float* __restrict__ inp,
        const float* __restrict__ Wq, const float* __restrict__ Wk,
        const float* __restrict__ Wv,
        const float* __restrict__ aq, const float* __restrict__ ak,
        const float* __restrict__ av) {
    __shared__ float As[2][8][128];
    __shared__ float Bs[2][8][128];
    int b  = blockIdx.z;
    int n0 = blockIdx.x * 128;
    int m0 = blockIdx.y * 128;
    int jm = n0 >> 10, jn0 = n0 & 1023;
    const float* W = (jm == 0) ? Wq : ((jm == 1) ? Wk : Wv);
    float al = (jm == 0) ? aq[0] : ((jm == 1) ? ak[0] : av[0]);
    float scale = 1.0f / (1.0f + fast_exp(-al));

    int t  = threadIdx.x;
    int lk = t >> 5, lx = (t & 31) * 4;
    int ty = t >> 4, tx = t & 15;
    const float* Ag = inp + b * CIN * SEQ + lk * SEQ + m0 + lx;
    const float* Bg = W + lk * 1024 + jn0 + lx;

    float4 a = *(const float4*)Ag;
    float4 w = *(const float4*)Bg;
    *(float4*)&As[0][lk][lx] = a;
    Bs[0][lk][BPERM(lx + 0)] = w.x;
    Bs[0][lk][BPERM(lx + 1)] = w.y;
    Bs[0][lk][BPERM(lx + 2)] = w.z;
    Bs[0][lk][BPERM(lx + 3)] = w.w;
    __syncthreads();

    float acc[8][8] = {};
    for (int ct = 0; ct < 64; ct++) {
        int buf = ct & 1;
        if (ct < 63) {
            a = *(const float4*)(Ag + (ct + 1) * 8 * SEQ);
            w = *(const float4*)(Bg + (ct + 1) * 8 * 1024);
        }
#pragma unroll
        for (int kk = 0; kk < 8; kk++) {
            float ar[8], br[8];
            *(float4*)&ar[0] = *(const float4*)&As[buf][kk][ty * 8];
            *(float4*)&ar[4] = *(const float4*)&As[buf][kk][ty * 8 + 4];
            *(float4*)&br[0] = *(const float4*)&Bs[buf][kk][tx * 8];
            *(float4*)&br[4] = *(const float4*)&Bs[buf][kk][tx * 8 + 4];
#pragma unroll
            for (int i = 0; i < 8; i++)
#pragma unroll
                for (int j = 0; j < 8; j++)
                    acc[i][j] = fmaf(ar[i], br[j], acc[i][j]);
        }
        if (ct < 63) {
            int nb = buf ^ 1;
            *(float4*)&As[nb][lk][lx] = a;
            Bs[nb][lk][BPERM(lx + 0)] = w.x;
            Bs[nb][lk][BPERM(lx + 1)] = w.y;
            Bs[nb][lk][BPERM(lx + 2)] = w.z;
            Bs[nb][lk][BPERM(lx + 3)] = w.w;
        }
        __syncthreads();
    }
    // epilogue: acc[i][j] = C[s = m0+ty*8+i][j = jn0 + j*16 + tx] -> h = tx, d = (jn0>>4)+j
    int dbase = jn0 >> 4;
    int h = tx;
#pragma unroll
    for (int i = 0; i < 8; i++) {
        int s = m0 + ty * 8 + i;
        float4 v0 = make_float4(acc[i][0] * scale, acc[i][1] * scale, acc[i][2] * scale, acc[i][3] * scale);
        float4 v1 = make_float4(acc[i][4] * scale, acc[i][5] * scale, acc[i][6] * scale, acc[i][7] * scale);
        if (jm == 0) {
            float* p = g_Q + b * 1048576 + s * 1024 + h * 64 + dbase;
            *(float4*)p = v0; *(float4*)(p + 4) = v1;
        } else if (jm == 1) {
            float* p = g_K + b * 1048576 + s * 1024 + h * 64 + dbase;
            *(float4*)p = v0; *(float4*)(p + 4) = v1;
        } else {
            float* p = g_V + b * 1048576 + h * 65536 + s * 64 + dbase;
            *(float4*)p = v0; *(float4*)(p + 4) = v1;
        }
    }
}

// ================= K2: J = Q.K^T per (b,h); K=64 single-shot, 8x8 micro =================
__global__ __launch_bounds__(256) void k2_J() {
    extern __shared__ float sm[];
    float* As = sm;              // [64][132]  (d-major, q fast)
    float* Bs = sm + 64 * 132;   // [64][132]  (d-major, k fast)
    int bh = blockIdx.z;
    int b = bh >> 4, h = bh & 15;
    int q0 = blockIdx.y * 128, k0 = blockIdx.x * 128;
    const float* Qb = g_Q + b * 1048576 + h * 64;
    const float* Kb = g_K + b * 1048576 + h * 64;

    int t = threadIdx.x;
    int r = t >> 1, c4 = (t & 1) * 4;
#pragma unroll
    for (int i = 0; i < 8; i++) {
        int d = i * 8 + c4;
        float4 aq = *(const float4*)&Qb[(q0 + r) * 1024 + d];
        As[(d + 0) * 132 + r] = aq.x; As[(d + 1) * 132 + r] = aq.y;
        As[(d + 2) * 132 + r] = aq.z; As[(d + 3) * 132 + r] = aq.w;
        float4 bk = *(const float4*)&Kb[(k0 + r) * 1024 + d];
        Bs[(d + 0) * 132 + r] = bk.x; Bs[(d + 1) * 132 + r] = bk.y;
        Bs[(d + 2) * 132 + r] = bk.z; Bs[(d + 3) * 132 + r] = bk.w;
    }
    __syncthreads();

    int ty = t >> 4, tx = t & 15;
    float acc[8][8] = {};
#pragma unroll 8
    for (int kk = 0; kk < 64; kk++) {
        float ar[8], br[8];
        *(float4*)&ar[0] = *(const float4*)&As[kk * 132 + ty * 8];
        *(float4*)&ar[4] = *(const float4*)&As[kk * 132 + ty * 8 + 4];
        *(float4*)&br[0] = *(const float4*)&Bs[kk * 132 + tx * 8];
        *(float4*)&br[4] = *(const float4*)&Bs[kk * 132 + tx * 8 + 4];
#pragma unroll
        for (int i = 0; i < 8; i++)
#pragma unroll
            for (int j = 0; j < 8; j++)
                acc[i][j] = fmaf(ar[i], br[j], acc[i][j]);
    }
    float* Jp = g_J + ((size_t)bh << 20);
#pragma unroll
    for (int i = 0; i < 8; i++) {
        size_t row = (size_t)(q0 + ty * 8 + i) * 1024 + k0 + tx * 8;
        *(float4*)&Jp[row]     = make_float4(acc[i][0], acc[i][1], acc[i][2], acc[i][3]);
        *(float4*)&Jp[row + 4] = make_float4(acc[i][4], acc[i][5], acc[i][6], acc[i][7]);
    }
}

// ====== K34: per (b,q): EL = J@Wl - mask, softmax over k, U = W@Ww ======
__global__ void k34_softmax_U(const float* __restrict__ mask,
                              const float* __restrict__ Wl,
                              const float* __restrict__ Ww) {
    extern __shared__ float sE[];       // [1024][17]
    __shared__ float sWl[256];
    __shared__ float sWw[256];
    __shared__ float red[8][16];
    __shared__ float sInv[16];

    int q = blockIdx.x, b = blockIdx.y;
    int tid = threadIdx.x;
    sWl[tid] = Wl[tid & 255];
    sWw[tid] = Ww[tid & 255];
    __syncthreads();

    const float* Jb = g_J + (size_t)b * 16777216 + (size_t)q * 1024;
    float psum[16] = {};

    for (int k = tid; k < 1024; k += 256) {
        float j[16];
#pragma unroll
        for (int h = 0; h < 16; h++) j[h] = Jb[(size_t)h * 1048576 + k];
        float mk = mask[b * 1024 + k];
#pragma unroll
        for (int g = 0; g < 16; g++) {
            float el = -mk;
#pragma unroll
            for (int h = 0; h < 16; h++) el = fmaf(j[h], sWl[h * 16 + g], el);
            float e = fast_exp(el);
            sE[k * 17 + g] = e;
            psum[g] += e;
        }
    }
#pragma unroll
    for (int g = 0; g < 16; g++) {
        float v = psum[g];
#pragma unroll
        for (int off = 16; off > 0; off >>= 1)
            v += __shfl_down_sync(0xffffffff, v, off);
        if ((tid & 31) == 0) red[tid >> 5][g] = v;
    }
    __syncthreads();
    if (tid < 16) {
        float tsum = 0.f;
#pragma unroll
        for (int w = 0; w < 8; w++) tsum += red[w][tid];
        sInv[tid] = 1.0f / tsum;
    }
    __syncthreads();

    float* Ub = g_U + (size_t)b * 16777216 + (size_t)q * 1024;
    for (int k = tid; k < 1024; k += 256) {
        float e[16];
#pragma unroll
        for (int g = 0; g < 16; g++) e[g] = sE[k * 17 + g] * sInv[g];
#pragma unroll
        for (int v = 0; v < 16; v++) {
            float u = 0.f;
#pragma unroll
            for (int g = 0; g < 16; g++) u = fmaf(e[g], sWw[g * 16 + v], u);
            Ub[(size_t)v * 1048576 + k] = u;
        }
    }
}

// ================= K5: O = U.V per (b,v); 128x64, KC=16 DB, 8x4 micro =================
__global__ __launch_bounds__(256) void k5_O() {
    __shared__ float As[2][16 * 132];
    __shared__ float Bs[2][16 * 64];
    int bv = blockIdx.y;
    int b = bv >> 4, v = bv & 15;
    int q0 = blockIdx.x * 128;
    const float* U  = g_U + ((size_t)bv << 20);
    const float* Vp = g_V + b * 1048576 + v * 65536;

    int t = threadIdx.x;
    int arr = t & 127, kc = (t >> 7) * 8;    // A loader: row arr, k-offset kc..kc+7
    int bk = t >> 4, bn = (t & 15) * 4;      // B loader
    int ty = t >> 4, tx = t & 15;

    float4 a0 = *(const float4*)&U[(size_t)(q0 + arr) * 1024 + kc];
    float4 a1 = *(const float4*)&U[(size_t)(q0 + arr) * 1024 + kc + 4];
    float4 bb = *(const float4*)&Vp[bk * 64 + bn];
    As[0][(kc + 0) * 132 + arr] = a0.x; As[0][(kc + 1) * 132 + arr] = a0.y;
    As[0][(kc + 2) * 132 + arr] = a0.z; As[0][(kc + 3) * 132 + arr] = a0.w;
    As[0][(kc + 4) * 132 + arr] = a1.x; As[0][(kc + 5) * 132 + arr] = a1.y;
    As[0][(kc + 6) * 132 + arr] = a1.z; As[0][(kc + 7) * 132 + arr] = a1.w;
    *(float4*)&Bs[0][bk * 64 + bn] = bb;
    __syncthreads();

    float acc[8][4] = {};
    for (int ct = 0; ct < 64; ct++) {
        int buf = ct & 1;
        if (ct < 63) {
            int kn = (ct + 1) * 16;
            a0 = *(const float4*)&U[(size_t)(q0 + arr) * 1024 + kn + kc];
            a1 = *(const float4*)&U[(size_t)(q0 + arr) * 1024 + kn + kc + 4];
            bb = *(const float4*)&Vp[(kn + bk) * 64 + bn];
        }
#pragma unroll
        for (int kk = 0; kk < 16; kk++) {
            float ar[8], br[4];
            *(float4*)&ar[0] = *(const float4*)&As[buf][kk * 132 + ty * 8];
            *(float4*)&ar[4] = *(const float4*)&As[buf][kk * 132 + ty * 8 + 4];
            *(float4*)&br[0] = *(const float4*)&Bs[buf][kk * 64 + tx * 4];
#pragma unroll
            for (int i = 0; i < 8; i++)
#pragma unroll
                for (int j = 0; j < 4; j++)
                    acc[i][j] = fmaf(ar[i], br[j], acc[i][j]);
        }
        if (ct < 63) {
            int nb = buf ^ 1;
            As[nb][(kc + 0) * 132 + arr] = a0.x; As[nb][(kc + 1) * 132 + arr] = a0.y;
            As[nb][(kc + 2) * 132 + arr] = a0.z; As[nb][(kc + 3) * 132 + arr] = a0.w;
            As[nb][(kc + 4) * 132 + arr] = a1.x; As[nb][(kc + 5) * 132 + arr] = a1.y;
            As[nb][(kc + 6) * 132 + arr] = a1.z; As[nb][(kc + 7) * 132 + arr] = a1.w;
            *(float4*)&Bs[nb][bk * 64 + bn] = bb;
        }
        __syncthreads();
    }
#pragma unroll
    for (int i = 0; i < 8; i++) {
        int q = q0 + ty * 8 + i;
        *(float4*)&g_O[b * 1048576 + q * 1024 + v * 64 + tx * 4] =
            make_float4(acc[i][0], acc[i][1], acc[i][2], acc[i][3]);
    }
}

// ================= K6: partial C[c][q] = sum_j Wo'[j][c] * O[q][j], split-K=2 ====
__global__ __launch_bounds__(256) void k6_part(const float* __restrict__ Wo) {
    __shared__ float As[2][8][128];    // Wo cols (c fast)
    __shared__ float Bs[2][8 * 132];   // O transposed (j-major, q fast)
    int z = blockIdx.z;
    int b = z >> 1, ks = z & 1;
    int c0 = blockIdx.x * 128, q0 = blockIdx.y * 128;
    int jb = ks * 512;
    const float* Ob = g_O + b * 1048576;

    int t = threadIdx.x;
    int lk = t >> 5, lc = (t & 31) * 4;
    int nq = t >> 1, j4 = (t & 1) * 4;
    int ty = t >> 4, tx = t & 15;

    int j = jb + lk;
    int wrow = ((j & 63) << 4) | (j >> 6);
    float4 a = *(const float4*)&Wo[wrow * 512 + c0 + lc];
    float4 o = *(const float4*)&Ob[(q0 + nq) * 1024 + jb + j4];
    *(float4*)&As[0][lk][lc] = a;
    Bs[0][(j4 + 0) * 132 + nq] = o.x; Bs[0][(j4 + 1) * 132 + nq] = o.y;
    Bs[0][(j4 + 2) * 132 + nq] = o.z; Bs[0][(j4 + 3) * 132 + nq] = o.w;
    __syncthreads();

    float acc[8][8] = {};
    for (int ct = 0; ct < 64; ct++) {
        int buf = ct & 1;
        if (ct < 63) {
            j = jb + (ct + 1) * 8 + lk;
            wrow = ((j & 63) << 4) | (j >> 6);
            a = *(const float4*)&Wo[wrow * 512 + c0 + lc];
            o = *(const float4*)&Ob[(q0 + nq) * 1024 + jb + (ct + 1) * 8 + j4];
        }
#pragma unroll
        for (int kk = 0; kk < 8; kk++) {
            float ar[8], br[8];
            *(float4*)&ar[0] = *(const float4*)&As[buf][kk][ty * 8];
            *(float4*)&ar[4] = *(const float4*)&As[buf][kk][ty * 8 + 4];
            *(float4*)&br[0] = *(const float4*)&Bs[buf][kk * 132 + tx * 8];
            *(float4*)&br[4] = *(const float4*)&Bs[buf][kk * 132 + tx * 8 + 4];
#pragma unroll
            for (int i = 0; i < 8; i++)
#pragma unroll
                for (int jj = 0; jj < 8; jj++)
                    acc[i][jj] = fmaf(ar[i], br[jj], acc[i][jj]);
        }
        if (ct < 63) {
            int nb = buf ^ 1;
            *(float4*)&As[nb][lk][lc] = a;
            Bs[nb][(j4 + 0) * 132 + nq] = o.x; Bs[nb][(j4 + 1) * 132 + nq] = o.y;
            Bs[nb][(j4 + 2) * 132 + nq] = o.z; Bs[nb][(j4 + 3) * 132 + nq] = o.w;
        }
        __syncthreads();
    }
    float* Pp = g_P + (size_t)z * 524288;
#pragma unroll
    for (int i = 0; i < 8; i++) {
        size_t row = (size_t)(c0 + ty * 8 + i) * 1024 + q0 + tx * 8;
        *(float4*)&Pp[row]     = make_float4(acc[i][0], acc[i][1], acc[i][2], acc[i][3]);
        *(float4*)&Pp[row + 4] = make_float4(acc[i][4], acc[i][5], acc[i][6], acc[i][7]);
    }
}

// ================= K7: out = inp + P0 + P1 =================
__global__ void k7_combine(const float* __restrict__ inp, float* __restrict__ out) {
    int gid = blockIdx.x * 256 + threadIdx.x;     // 0..262143 float4s
    size_t fl = (size_t)gid * 4;
    int b = (int)(fl >> 19);
    size_t loc = fl & 524287;
    float4 iv = *(const float4*)(inp + fl);
    float4 p0 = *(const float4*)(g_P + (size_t)b * 1048576 + loc);
    float4 p1 = *(const float4*)(g_P + (size_t)b * 1048576 + 524288 + loc);
    *(float4*)(out + fl) = make_float4(iv.x + p0.x + p1.x, iv.y + p0.y + p1.y,
                                       iv.z + p0.z + p1.z, iv.w + p0.w + p1.w);
}

// ================= launch =================
extern "C" void kernel_launch(void* const* d_in, const int* in_sizes, int n_in,
                              void* d_out, int out_size) {
    const float* inp  = (const float*)d_in[0];
    const float* mask = (const float*)d_in[1];
    const float* Wq   = (const float*)d_in[2];
    const float* Wk   = (const float*)d_in[3];
    const float* Wv   = (const float*)d_in[4];
    const float* aq   = (const float*)d_in[5];
    const float* ak   = (const float*)d_in[6];
    const float* av   = (const float*)d_in[7];
    const float* Wl   = (const float*)d_in[8];
    const float* Ww   = (const float*)d_in[9];
    const float* Wo   = (const float*)d_in[10];
    float* out = (float*)d_out;

    const int SMEM_K2  = 2 * 64 * 132 * 4;  // 67584
    const int SMEM_K34 = 1024 * 17 * 4;     // 69632
    cudaFuncSetAttribute(k2_J, cudaFuncAttributeMaxDynamicSharedMemorySize, SMEM_K2);
    cudaFuncSetAttribute(k34_softmax_U, cudaFuncAttributeMaxDynamicSharedMemorySize, SMEM_K34);

    k1_proj<<<dim3(24, 8, 2), 256>>>(inp, Wq, Wk, Wv, aq, ak, av);
    k2_J<<<dim3(8, 8, 32), 256, SMEM_K2>>>();
    k34_softmax_U<<<dim3(1024, 2), 256, SMEM_K34>>>(mask, Wl, Ww);
    k5_O<<<dim3(8, 32), 256>>>();
    k6_part<<<dim3(4, 8, 4), 256>>>(Wo);
    k7_combine<<<1024, 256>>>(inp, out);
}

// round 3
// speedup vs baseline: 1.2900x; 1.2635x over previous
#include <cuda_runtime.h>
#include <cuda_fp16.h>
#include <cstdint>

#define CIN 512
#define SEQ 1024

// ---------------- scratch ----------------
__device__ float  g_Q[2 * 1024 * 1024];              // [b][s][h*64+d]
__device__ float  g_K[2 * 1024 * 1024];              // [b][s][h*64+d]
__device__ float  g_V[2 * 1024 * 1024];              // [b][h][k][d]
__device__ __half g_J[(size_t)2 * 16 * 1024 * 1024]; // [b][h][q][k]  64 MB
__device__ __half g_U[(size_t)2 * 16 * 1024 * 1024]; // [b][v][q][k]  64 MB (scaled x256)
__device__ float  g_O[2 * 1024 * 1024];              // [b][q][v*64+d]
__device__ float  g_P[4 * 512 * 1024];               // split-K partials for k6

#define USCALE 256.0f
#define UINV   (1.0f / 256.0f)

// ---------------- fast exp on the FMA pipe ----------------
__device__ __forceinline__ float fast_exp(float x) {
    float t  = fmaf(x, 1.4426950408889634f, 12582912.0f);
    float fi = t - 12582912.0f;
    float f  = fmaf(x, 1.4426950408889634f, -fi);
    int   n  = __float_as_int(t) - 0x4B400000;
    float p  = 1.33335581e-3f;
    p = fmaf(p, f, 9.61812911e-3f);
    p = fmaf(p, f, 5.55041087e-2f);
    p = fmaf(p, f, 2.40226507e-1f);
    p = fmaf(p, f, 6.93147181e-1f);
    p = fmaf(p, f, 1.0f);
    return p * __int_as_float((n + 127) << 23);
}

#define BPERM(n) (((((n) & 15)) << 3) | ((n) >> 4))

// ================= K1: fused QKV projection (128x128x8 DB, 8x8 micro) =================
__global__ __launch_bounds__(256) void k1_proj(const float* __restrict__ inp,
        const float* __restrict__ Wq, const float* __restrict__ Wk,
        const float* __restrict__ Wv,
        const float* __restrict__ aq, const float* __restrict__ ak,
        const float* __restrict__ av) {
    __shared__ float As[2][8][128];
    __shared__ float Bs[2][8][128];
    int b  = blockIdx.z;
    int n0 = blockIdx.x * 128;
    int m0 = blockIdx.y * 128;
    int jm = n0 >> 10, jn0 = n0 & 1023;
    const float* W = (jm == 0) ? Wq : ((jm == 1) ? Wk : Wv);
    float al = (jm == 0) ? aq[0] : ((jm == 1) ? ak[0] : av[0]);
    float scale = 1.0f / (1.0f + fast_exp(-al));

    int t  = threadIdx.x;
    int lk = t >> 5, lx = (t & 31) * 4;
    int ty = t >> 4, tx = t & 15;
    const float* Ag = inp + b * CIN * SEQ + lk * SEQ + m0 + lx;
    const float* Bg = W + lk * 1024 + jn0 + lx;

    float4 a = *(const float4*)Ag;
    float4 w = *(const float4*)Bg;
    *(float4*)&As[0][lk][lx] = a;
    Bs[0][lk][BPERM(lx + 0)] = w.x;
    Bs[0][lk][BPERM(lx + 1)] = w.y;
    Bs[0][lk][BPERM(lx + 2)] = w.z;
    Bs[0][lk][BPERM(lx + 3)] = w.w;
    __syncthreads();

    float acc[8][8] = {};
    for (int ct = 0; ct < 64; ct++) {
        int buf = ct & 1;
        if (ct < 63) {
            a = *(const float4*)(Ag + (ct + 1) * 8 * SEQ);
            w = *(const float4*)(Bg + (ct + 1) * 8 * 1024);
        }
#pragma unroll
        for (int kk = 0; kk < 8; kk++) {
            float ar[8], br[8];
            *(float4*)&ar[0] = *(const float4*)&As[buf][kk][ty * 8];
            *(float4*)&ar[4] = *(const float4*)&As[buf][kk][ty * 8 + 4];
            *(float4*)&br[0] = *(const float4*)&Bs[buf][kk][tx * 8];
            *(float4*)&br[4] = *(const float4*)&Bs[buf][kk][tx * 8 + 4];
#pragma unroll
            for (int i = 0; i < 8; i++)
#pragma unroll
                for (int j = 0; j < 8; j++)
                    acc[i][j] = fmaf(ar[i], br[j], acc[i][j]);
        }
        if (ct < 63) {
            int nb = buf ^ 1;
            *(float4*)&As[nb][lk][lx] = a;
            Bs[nb][lk][BPERM(lx + 0)] = w.x;
            Bs[nb][lk][BPERM(lx + 1)] = w.y;
            Bs[nb][lk][BPERM(lx + 2)] = w.z;
            Bs[nb][lk][BPERM(lx + 3)] = w.w;
        }
        __syncthreads();
    }
    int dbase = jn0 >> 4;
    int h = tx;
#pragma unroll
    for (int i = 0; i < 8; i++) {
        int s = m0 + ty * 8 + i;
        float4 v0 = make_float4(acc[i][0] * scale, acc[i][1] * scale, acc[i][2] * scale, acc[i][3] * scale);
        float4 v1 = make_float4(acc[i][4] * scale, acc[i][5] * scale, acc[i][6] * scale, acc[i][7] * scale);
        if (jm == 0) {
            float* p = g_Q + b * 1048576 + s * 1024 + h * 64 + dbase;
            *(float4*)p = v0; *(float4*)(p + 4) = v1;
        } else if (jm == 1) {
            float* p = g_K + b * 1048576 + s * 1024 + h * 64 + dbase;
            *(float4*)p = v0; *(float4*)(p + 4) = v1;
        } else {
            float* p = g_V + b * 1048576 + h * 65536 + s * 64 + dbase;
            *(float4*)p = v0; *(float4*)(p + 4) = v1;
        }
    }
}

// ================= K2: J = Q.K^T per (b,h); K=64 single-shot, 8x8 micro, fp16 out ======
__global__ __launch_bounds__(256) void k2_J() {
    extern __shared__ float sm[];
    float* As = sm;              // [64][132]
    float* Bs = sm + 64 * 132;   // [64][132]
    int bh = blockIdx.z;
    int b = bh >> 4, h = bh & 15;
    int q0 = blockIdx.y * 128, k0 = blockIdx.x * 128;
    const float* Qb = g_Q + b * 1048576 + h * 64;
    const float* Kb = g_K + b * 1048576 + h * 64;

    int t = threadIdx.x;
    int r = t >> 1, c4 = (t & 1) * 4;
#pragma unroll
    for (int i = 0; i < 8; i++) {
        int d = i * 8 + c4;
        float4 aq = *(const float4*)&Qb[(q0 + r) * 1024 + d];
        As[(d + 0) * 132 + r] = aq.x; As[(d + 1) * 132 + r] = aq.y;
        As[(d + 2) * 132 + r] = aq.z; As[(d + 3) * 132 + r] = aq.w;
        float4 bk = *(const float4*)&Kb[(k0 + r) * 1024 + d];
        Bs[(d + 0) * 132 + r] = bk.x; Bs[(d + 1) * 132 + r] = bk.y;
        Bs[(d + 2) * 132 + r] = bk.z; Bs[(d + 3) * 132 + r] = bk.w;
    }
    __syncthreads();

    int ty = t >> 4, tx = t & 15;
    float acc[8][8] = {};
#pragma unroll 8
    for (int kk = 0; kk < 64; kk++) {
        float ar[8], br[8];
        *(float4*)&ar[0] = *(const float4*)&As[kk * 132 + ty * 8];
        *(float4*)&ar[4] = *(const float4*)&As[kk * 132 + ty * 8 + 4];
        *(float4*)&br[0] = *(const float4*)&Bs[kk * 132 + tx * 8];
        *(float4*)&br[4] = *(const float4*)&Bs[kk * 132 + tx * 8 + 4];
#pragma unroll
        for (int i = 0; i < 8; i++)
#pragma unroll
            for (int j = 0; j < 8; j++)
                acc[i][j] = fmaf(ar[i], br[j], acc[i][j]);
    }
    __half* Jp = g_J + ((size_t)bh << 20);
#pragma unroll
    for (int i = 0; i < 8; i++) {
        size_t row = (size_t)(q0 + ty * 8 + i) * 1024 + k0 + tx * 8;
        __half hv[8];
#pragma unroll
        for (int j = 0; j < 8; j++) hv[j] = __float2half_rn(acc[i][j]);
        *(uint4*)&g_J[((size_t)bh << 20) + row] = *(uint4*)hv;
        (void)Jp;
    }
}

// ====== K34: per (b,q): EL = J@Wl - mask, softmax over k, U = W@Ww (fp16 I/O) ======
__global__ void k34_softmax_U(const float* __restrict__ mask,
                              const float* __restrict__ Wl,
                              const float* __restrict__ Ww) {
    extern __shared__ float sE[];       // [1024][17]
    __shared__ float sWl[256];
    __shared__ float sWw[256];
    __shared__ float red[8][16];
    __shared__ float sInv[16];

    int q = blockIdx.x, b = blockIdx.y;
    int tid = threadIdx.x;
    sWl[tid] = Wl[tid & 255];
    sWw[tid] = Ww[tid & 255];
    __syncthreads();

    const __half* Jb = g_J + (size_t)b * 16777216 + (size_t)q * 1024;
    float psum[16] = {};

#pragma unroll
    for (int it = 0; it < 2; it++) {
        int k = it * 512 + tid * 2;
        float j0[16], j1[16];
#pragma unroll
        for (int h = 0; h < 16; h++) {
            __half2 jj = *(const __half2*)&Jb[(size_t)h * 1048576 + k];
            float2 f = __half22float2(jj);
            j0[h] = f.x; j1[h] = f.y;
        }
        float mk0 = mask[b * 1024 + k];
        float mk1 = mask[b * 1024 + k + 1];
#pragma unroll
        for (int g = 0; g < 16; g++) {
            float el0 = -mk0, el1 = -mk1;
#pragma unroll
            for (int h = 0; h < 16; h++) {
                float wl = sWl[h * 16 + g];
                el0 = fmaf(j0[h], wl, el0);
                el1 = fmaf(j1[h], wl, el1);
            }
            float e0 = fast_exp(el0);
            float e1 = fast_exp(el1);
            sE[k * 17 + g] = e0;
            sE[(k + 1) * 17 + g] = e1;
            psum[g] += e0 + e1;
        }
    }
#pragma unroll
    for (int g = 0; g < 16; g++) {
        float v = psum[g];
#pragma unroll
        for (int off = 16; off > 0; off >>= 1)
            v += __shfl_down_sync(0xffffffff, v, off);
        if ((tid & 31) == 0) red[tid >> 5][g] = v;
    }
    __syncthreads();
    if (tid < 16) {
        float tsum = 0.f;
#pragma unroll
        for (int w = 0; w < 8; w++) tsum += red[w][tid];
        sInv[tid] = USCALE / tsum;   // fold the fp16 range scale into the normalizer
    }
    __syncthreads();

    __half* Ub = g_U + (size_t)b * 16777216 + (size_t)q * 1024;
#pragma unroll
    for (int it = 0; it < 2; it++) {
        int k = it * 512 + tid * 2;
        float e0[16], e1[16];
#pragma unroll
        for (int g = 0; g < 16; g++) {
            e0[g] = sE[k * 17 + g] * sInv[g];
            e1[g] = sE[(k + 1) * 17 + g] * sInv[g];
        }
#pragma unroll
        for (int v = 0; v < 16; v++) {
            float u0 = 0.f, u1 = 0.f;
#pragma unroll
            for (int g = 0; g < 16; g++) {
                float ww = sWw[g * 16 + v];
                u0 = fmaf(e0[g], ww, u0);
                u1 = fmaf(e1[g], ww, u1);
            }
            *(__half2*)&Ub[(size_t)v * 1048576 + k] = __floats2half2_rn(u0, u1);
        }
    }
}

// ================= K5: O = U.V per (b,v); 128x64, KC=16 DB, 8x4 micro, fp16 A ======
__global__ __launch_bounds__(256) void k5_O() {
    __shared__ float As[2][16 * 132];
    __shared__ float Bs[2][16 * 64];
    int bv = blockIdx.y;
    int b = bv >> 4, v = bv & 15;
    int q0 = blockIdx.x * 128;
    const __half* U = g_U + ((size_t)bv << 20);
    const float* Vp = g_V + b * 1048576 + v * 65536;

    int t = threadIdx.x;
    int arr = t & 127, kc = (t >> 7) * 8;
    int bk = t >> 4, bn = (t & 15) * 4;
    int ty = t >> 4, tx = t & 15;

    uint4 araw = *(const uint4*)&U[(size_t)(q0 + arr) * 1024 + kc];
    float4 bb = *(const float4*)&Vp[bk * 64 + bn];
    {
        __half2* hp = (__half2*)&araw;
#pragma unroll
        for (int p = 0; p < 4; p++) {
            float2 f = __half22float2(hp[p]);
            As[0][(kc + p * 2 + 0) * 132 + arr] = f.x;
            As[0][(kc + p * 2 + 1) * 132 + arr] = f.y;
        }
    }
    *(float4*)&Bs[0][bk * 64 + bn] = bb;
    __syncthreads();

    float acc[8][4] = {};
    for (int ct = 0; ct < 64; ct++) {
        int buf = ct & 1;
        if (ct < 63) {
            int kn = (ct + 1) * 16;
            araw = *(const uint4*)&U[(size_t)(q0 + arr) * 1024 + kn + kc];
            bb = *(const float4*)&Vp[(kn + bk) * 64 + bn];
        }
#pragma unroll
        for (int kk = 0; kk < 16; kk++) {
            float ar[8], br[4];
            *(float4*)&ar[0] = *(const float4*)&As[buf][kk * 132 + ty * 8];
            *(float4*)&ar[4] = *(const float4*)&As[buf][kk * 132 + ty * 8 + 4];
            *(float4*)&br[0] = *(const float4*)&Bs[buf][kk * 64 + tx * 4];
#pragma unroll
            for (int i = 0; i < 8; i++)
#pragma unroll
                for (int j = 0; j < 4; j++)
                    acc[i][j] = fmaf(ar[i], br[j], acc[i][j]);
        }
        if (ct < 63) {
            int nb = buf ^ 1;
            __half2* hp = (__half2*)&araw;
#pragma unroll
            for (int p = 0; p < 4; p++) {
                float2 f = __half22float2(hp[p]);
                As[nb][(kc + p * 2 + 0) * 132 + arr] = f.x;
                As[nb][(kc + p * 2 + 1) * 132 + arr] = f.y;
            }
            *(float4*)&Bs[nb][bk * 64 + bn] = bb;
        }
        __syncthreads();
    }
#pragma unroll
    for (int i = 0; i < 8; i++) {
        int q = q0 + ty * 8 + i;
        *(float4*)&g_O[b * 1048576 + q * 1024 + v * 64 + tx * 4] =
            make_float4(acc[i][0] * UINV, acc[i][1] * UINV, acc[i][2] * UINV, acc[i][3] * UINV);
    }
}

// ================= K6: partial C[c][q] = sum_j Wo'[j][c] * O[q][j], split-K=2 ====
__global__ __launch_bounds__(256) void k6_part(const float* __restrict__ Wo) {
    __shared__ float As[2][8][128];
    __shared__ float Bs[2][8 * 132];
    int z = blockIdx.z;
    int b = z >> 1, ks = z & 1;
    int c0 = blockIdx.x * 128, q0 = blockIdx.y * 128;
    int jb = ks * 512;
    const float* Ob = g_O + b * 1048576;

    int t = threadIdx.x;
    int lk = t >> 5, lc = (t & 31) * 4;
    int nq = t >> 1, j4 = (t & 1) * 4;
    int ty = t >> 4, tx = t & 15;

    int j = jb + lk;
    int wrow = ((j & 63) << 4) | (j >> 6);
    float4 a = *(const float4*)&Wo[wrow * 512 + c0 + lc];
    float4 o = *(const float4*)&Ob[(q0 + nq) * 1024 + jb + j4];
    *(float4*)&As[0][lk][lc] = a;
    Bs[0][(j4 + 0) * 132 + nq] = o.x; Bs[0][(j4 + 1) * 132 + nq] = o.y;
    Bs[0][(j4 + 2) * 132 + nq] = o.z; Bs[0][(j4 + 3) * 132 + nq] = o.w;
    __syncthreads();

    float acc[8][8] = {};
    for (int ct = 0; ct < 64; ct++) {
        int buf = ct & 1;
        if (ct < 63) {
            j = jb + (ct + 1) * 8 + lk;
            wrow = ((j & 63) << 4) | (j >> 6);
            a = *(const float4*)&Wo[wrow * 512 + c0 + lc];
            o = *(const float4*)&Ob[(q0 + nq) * 1024 + jb + (ct + 1) * 8 + j4];
        }
#pragma unroll
        for (int kk = 0; kk < 8; kk++) {
            float ar[8], br[8];
            *(float4*)&ar[0] = *(const float4*)&As[buf][kk][ty * 8];
            *(float4*)&ar[4] = *(const float4*)&As[buf][kk][ty * 8 + 4];
            *(float4*)&br[0] = *(const float4*)&Bs[buf][kk * 132 + tx * 8];
            *(float4*)&br[4] = *(const float4*)&Bs[buf][kk * 132 + tx * 8 + 4];
#pragma unroll
            for (int i = 0; i < 8; i++)
#pragma unroll
                for (int jj = 0; jj < 8; jj++)
                    acc[i][jj] = fmaf(ar[i], br[jj], acc[i][jj]);
        }
        if (ct < 63) {
            int nb = buf ^ 1;
            *(float4*)&As[nb][lk][lc] = a;
            Bs[nb][(j4 + 0) * 132 + nq] = o.x; Bs[nb][(j4 + 1) * 132 + nq] = o.y;
            Bs[nb][(j4 + 2) * 132 + nq] = o.z; Bs[nb][(j4 + 3) * 132 + nq] = o.w;
        }
        __syncthreads();
    }
    float* Pp = g_P + (size_t)z * 524288;
#pragma unroll
    for (int i = 0; i < 8; i++) {
        size_t row = (size_t)(c0 + ty * 8 + i) * 1024 + q0 + tx * 8;
        *(float4*)&Pp[row]     = make_float4(acc[i][0], acc[i][1], acc[i][2], acc[i][3]);
        *(float4*)&Pp[row + 4] = make_float4(acc[i][4], acc[i][5], acc[i][6], acc[i][7]);
    }
}

// ================= K7: out = inp + P0 + P1 =================
__global__ void k7_combine(const float* __restrict__ inp, float* __restrict__ out) {
    int gid = blockIdx.x * 256 + threadIdx.x;
    size_t fl = (size_t)gid * 4;
    int b = (int)(fl >> 19);
    size_t loc = fl & 524287;
    float4 iv = *(const float4*)(inp + fl);
    float4 p0 = *(const float4*)(g_P + (size_t)b * 1048576 + loc);
    float4 p1 = *(const float4*)(g_P + (size_t)b * 1048576 + 524288 + loc);
    *(float4*)(out + fl) = make_float4(iv.x + p0.x + p1.x, iv.y + p0.y + p1.y,
                                       iv.z + p0.z + p1.z, iv.w + p0.w + p1.w);
}

// ================= launch =================
extern "C" void kernel_launch(void* const* d_in, const int* in_sizes, int n_in,
                              void* d_out, int out_size) {
    const float* inp  = (const float*)d_in[0];
    const float* mask = (const float*)d_in[1];
    const float* Wq   = (const float*)d_in[2];
    const float* Wk   = (const float*)d_in[3];
    const float* Wv   = (const float*)d_in[4];
    const float* aq   = (const float*)d_in[5];
    const float* ak   = (const float*)d_in[6];
    const float* av   = (const float*)d_in[7];
    const float* Wl   = (const float*)d_in[8];
    const float* Ww   = (const float*)d_in[9];
    const float* Wo   = (const float*)d_in[10];
    float* out = (float*)d_out;

    const int SMEM_K2  = 2 * 64 * 132 * 4;  // 67584
    const int SMEM_K34 = 1024 * 17 * 4;     // 69632
    cudaFuncSetAttribute(k2_J, cudaFuncAttributeMaxDynamicSharedMemorySize, SMEM_K2);
    cudaFuncSetAttribute(k34_softmax_U, cudaFuncAttributeMaxDynamicSharedMemorySize, SMEM_K34);

    k1_proj<<<dim3(24, 8, 2), 256>>>(inp, Wq, Wk, Wv, aq, ak, av);
    k2_J<<<dim3(8, 8, 32), 256, SMEM_K2>>>();
    k34_softmax_U<<<dim3(1024, 2), 256, SMEM_K34>>>(mask, Wl, Ww);
    k5_O<<<dim3(8, 32), 256>>>();
    k6_part<<<dim3(4, 8, 4), 256>>>(Wo);
    k7_combine<<<1024, 256>>>(inp, out);
}

// round 4
// speedup vs baseline: 2.7329x; 2.1185x over previous
#include <cuda_runtime.h>
#include <cuda_fp16.h>
#include <cstdint>

#define CIN 512
#define SEQ 1024

// ---------------- scratch ----------------
__device__ __half g_inp16[2 * 512 * 1024];           // [b][c][s]   2 MB
__device__ __half g_W16[3 * 512 * 1024];             // [w][c][h*64+d] scale-folded, 3 MB
__device__ __half g_Qh[2 * 16 * 1024 * 64];          // [b][h][s][d] 4 MB
__device__ __half g_Kh[2 * 16 * 1024 * 64];          // [b][h][s][d] 4 MB
__device__ __half g_Vh[2 * 16 * 1024 * 64];          // [b][h][k][d] 4 MB
__device__ __half g_J[(size_t)2 * 16 * 1024 * 1024]; // [b][h][q][k] 64 MB
__device__ __half g_U[(size_t)2 * 16 * 1024 * 1024]; // [b][v][q][k] 64 MB (x256)
__device__ float  g_O[2 * 1024 * 1024];              // [b][q][v*64+d]
__device__ float  g_P[4 * 512 * 1024];               // split-K partials for k6

#define USCALE 256.0f
#define UINV   (1.0f / 256.0f)

// ---------------- fast exp on the FMA pipe ----------------
__device__ __forceinline__ float fast_exp(float x) {
    float t  = fmaf(x, 1.4426950408889634f, 12582912.0f);
    float fi = t - 12582912.0f;
    float f  = fmaf(x, 1.4426950408889634f, -fi);
    int   n  = __float_as_int(t) - 0x4B400000;
    float p  = 1.33335581e-3f;
    p = fmaf(p, f, 9.61812911e-3f);
    p = fmaf(p, f, 5.55041087e-2f);
    p = fmaf(p, f, 2.40226507e-1f);
    p = fmaf(p, f, 6.93147181e-1f);
    p = fmaf(p, f, 1.0f);
    return p * __int_as_float((n + 127) << 23);
}

// ---------------- mma helpers ----------------
__device__ __forceinline__ uint32_t cvta_s(const void* p) {
    return (uint32_t)__cvta_generic_to_shared(p);
}
__device__ __forceinline__ void ldm4(uint32_t* r, uint32_t a) {
    asm volatile("ldmatrix.sync.aligned.m8n8.x4.shared.b16 {%0,%1,%2,%3}, [%4];"
        : "=r"(r[0]), "=r"(r[1]), "=r"(r[2]), "=r"(r[3]) : "r"(a));
}
__device__ __forceinline__ void ldm4t(uint32_t* r, uint32_t a) {
    asm volatile("ldmatrix.sync.aligned.m8n8.x4.trans.shared.b16 {%0,%1,%2,%3}, [%4];"
        : "=r"(r[0]), "=r"(r[1]), "=r"(r[2]), "=r"(r[3]) : "r"(a));
}
__device__ __forceinline__ void mma16816(float* c, const uint32_t* a, const uint32_t* b) {
    asm volatile("mma.sync.aligned.m16n8k16.row.col.f32.f16.f16.f32 "
        "{%0,%1,%2,%3}, {%4,%5,%6,%7}, {%8,%9}, {%0,%1,%2,%3};"
        : "+f"(c[0]), "+f"(c[1]), "+f"(c[2]), "+f"(c[3])
        : "r"(a[0]), "r"(a[1]), "r"(a[2]), "r"(a[3]), "r"(b[0]), "r"(b[1]));
}

// ================= KC0: fp16 conversion + W reorder (j = d*16+h -> j' = h*64+d) ======
__global__ __launch_bounds__(256) void kc0(const float* __restrict__ inp,
        const float* __restrict__ Wq, const float* __restrict__ Wk,
        const float* __restrict__ Wv,
        const float* __restrict__ aq, const float* __restrict__ ak,
        const float* __restrict__ av) {
    int t = blockIdx.x * 256 + threadIdx.x;
    if (t < 524288) {
        float2 v = *(const float2*)(inp + (size_t)t * 2);
        *(__half2*)(g_inp16 + (size_t)t * 2) = __floats2half2_rn(v.x, v.y);
    }
    int u = t - 524288;
    if (u >= 0 && u < 3 * 262144) {
        int w = u / 262144, o = u % 262144;
        int c = o >> 9, jp = (o & 511) * 2;       // j' = jp, jp+1 (d even)
        int h = jp >> 6, d = jp & 63;
        const float* W = (w == 0) ? Wq : ((w == 1) ? Wk : Wv);
        float al = (w == 0) ? aq[0] : ((w == 1) ? ak[0] : av[0]);
        float sc = 1.0f / (1.0f + fast_exp(-al));
        float x0 = W[c * 1024 + d * 16 + h] * sc;
        float x1 = W[c * 1024 + (d + 1) * 16 + h] * sc;
        *(__half2*)(g_W16 + w * 524288 + c * 1024 + jp) = __floats2half2_rn(x0, x1);
    }
}

// ================= K1: QKV projection, HMMA, 128x128, KC=32 DB =================
// C[s][j'] = sum_c inp16[b][c][s] * W16[w][c][j'];  j' = h*64+d
__global__ __launch_bounds__(256) void k1_proj() {
    __shared__ __half As[2][32 * 136];   // [k=c][m=s]
    __shared__ __half Bs[2][32 * 136];   // [k=c][n=j']
    int z = blockIdx.z;
    int b = z / 3, w = z % 3;
    int n0 = blockIdx.x * 128, m0 = blockIdx.y * 128;
    const __half* Ag = g_inp16 + b * 524288;
    const __half* Bg = g_W16 + w * 524288;

    int t = threadIdx.x, lane = t & 31, warp = t >> 5;
    int lrow = t >> 3, lcol = (t & 7) * 16;   // 2 uint4 per matrix per chunk

    // initial chunk load
    {
        const uint4* as = (const uint4*)(Ag + lrow * 1024 + m0 + lcol);
        const uint4* bs = (const uint4*)(Bg + lrow * 1024 + n0 + lcol);
        uint4* ad = (uint4*)(As[0] + lrow * 136 + lcol);
        uint4* bd = (uint4*)(Bs[0] + lrow * 136 + lcol);
        ad[0] = as[0]; ad[1] = as[1];
        bd[0] = bs[0]; bd[1] = bs[1];
    }
    __syncthreads();

    int wm = (warp >> 2) * 64, wn = (warp & 3) * 32;
    // lane addressing (precompute lane-dependent parts)
    int a_r = (lane & 7) + ((lane & 16) ? 8 : 0);     // A trans: row k-offset
    int a_c = (lane & 8) ? 8 : 0;                     // A trans: col m-offset
    int b_r = (lane & 7) + ((lane & 8) ? 8 : 0);      // B trans: row k-offset
    int b_c = (lane & 16) ? 8 : 0;                    // B trans: col n-offset

    float acc[4][4][4] = {};
    for (int ch = 0; ch < 16; ch++) {
        int buf = ch & 1;
        uint4 pa0, pa1, pb0, pb1;
        if (ch < 15) {
            const uint4* as = (const uint4*)(Ag + ((ch + 1) * 32 + lrow) * 1024 + m0 + lcol);
            const uint4* bs = (const uint4*)(Bg + ((ch + 1) * 32 + lrow) * 1024 + n0 + lcol);
            pa0 = as[0]; pa1 = as[1];
            pb0 = bs[0]; pb1 = bs[1];
        }
#pragma unroll
        for (int ks = 0; ks < 2; ks++) {
            int kk = ks * 16;
            uint32_t af[4][4], bf[2][4];
#pragma unroll
            for (int mi = 0; mi < 4; mi++)
                ldm4t(af[mi], cvta_s(As[buf] + (kk + a_r) * 136 + wm + mi * 16 + a_c));
#pragma unroll
            for (int np = 0; np < 2; np++)
                ldm4t(bf[np], cvta_s(Bs[buf] + (kk + b_r) * 136 + wn + np * 16 + b_c));
#pragma unroll
            for (int mi = 0; mi < 4; mi++)
#pragma unroll
                for (int ni = 0; ni < 4; ni++)
                    mma16816(acc[mi][ni], af[mi], &bf[ni >> 1][(ni & 1) * 2]);
        }
        if (ch < 15) {
            int nb = buf ^ 1;
            uint4* ad = (uint4*)(As[nb] + lrow * 136 + lcol);
            uint4* bd = (uint4*)(Bs[nb] + lrow * 136 + lcol);
            ad[0] = pa0; ad[1] = pa1;
            bd[0] = pb0; bd[1] = pb1;
        }
        __syncthreads();
    }

    __half* base = (w == 0) ? g_Qh : ((w == 1) ? g_Kh : g_Vh);
    int row = lane >> 2, colp = (lane & 3) * 2;
#pragma unroll
    for (int mi = 0; mi < 4; mi++) {
        int s = m0 + wm + mi * 16 + row;
#pragma unroll
        for (int ni = 0; ni < 4; ni++) {
            int jp = n0 + wn + ni * 8 + colp;
            int h = jp >> 6, d = jp & 63;
            __half* p = base + (((b * 16 + h) * 1024 + s) << 6) + d;
            *(__half2*)p = __floats2half2_rn(acc[mi][ni][0], acc[mi][ni][1]);
            *(__half2*)(p + (8 << 6)) = __floats2half2_rn(acc[mi][ni][2], acc[mi][ni][3]);
        }
    }
}

// ================= K2: J = Q.K^T per (b,h), HMMA, 128x128, K=64 single-shot =========
__global__ __launch_bounds__(256) void k2_J() {
    __shared__ __half As[128 * 72];  // [q][d]
    __shared__ __half Bs[128 * 72];  // [k'][d]
    int bh = blockIdx.z;
    int q0 = blockIdx.y * 128, k0 = blockIdx.x * 128;
    const __half* Qb = g_Qh + ((size_t)bh << 16);
    const __half* Kb = g_Kh + ((size_t)bh << 16);

    int t = threadIdx.x, lane = t & 31, warp = t >> 5;
    {
        int lr = t >> 1, ls = (t & 1) * 32;
        const uint4* qs = (const uint4*)(Qb + ((q0 + lr) << 6) + ls);
        const uint4* ks = (const uint4*)(Kb + ((k0 + lr) << 6) + ls);
        uint4* ad = (uint4*)(As + lr * 72 + ls);
        uint4* bd = (uint4*)(Bs + lr * 72 + ls);
#pragma unroll
        for (int i = 0; i < 4; i++) { ad[i] = qs[i]; bd[i] = ks[i]; }
    }
    __syncthreads();

    int wm = (warp >> 2) * 64, wn = (warp & 3) * 32;
    int amr = lane & 15, akc = (lane >> 4) * 8;                 // A normal
    int bnr = (lane & 7) + ((lane & 16) ? 8 : 0);               // B normal: n row offset
    int bkc = (lane & 8) ? 8 : 0;                               // B normal: k col offset

    float acc[4][4][4] = {};
#pragma unroll
    for (int ks = 0; ks < 4; ks++) {
        int kk = ks * 16;
        uint32_t af[4][4], bf[2][4];
#pragma unroll
        for (int mi = 0; mi < 4; mi++)
            ldm4(af[mi], cvta_s(As + (wm + mi * 16 + amr) * 72 + kk + akc));
#pragma unroll
        for (int np = 0; np < 2; np++)
            ldm4(bf[np], cvta_s(Bs + (wn + np * 16 + bnr) * 72 + kk + bkc));
#pragma unroll
        for (int mi = 0; mi < 4; mi++)
#pragma unroll
            for (int ni = 0; ni < 4; ni++)
                mma16816(acc[mi][ni], af[mi], &bf[ni >> 1][(ni & 1) * 2]);
    }

    __half* Jp = g_J + ((size_t)bh << 20);
    int row = lane >> 2, colp = (lane & 3) * 2;
#pragma unroll
    for (int mi = 0; mi < 4; mi++) {
        int q = q0 + wm + mi * 16 + row;
#pragma unroll
        for (int ni = 0; ni < 4; ni++) {
            int kc = k0 + wn + ni * 8 + colp;
            *(__half2*)&Jp[(size_t)q * 1024 + kc] =
                __floats2half2_rn(acc[mi][ni][0], acc[mi][ni][1]);
            *(__half2*)&Jp[(size_t)(q + 8) * 1024 + kc] =
                __floats2half2_rn(acc[mi][ni][2], acc[mi][ni][3]);
        }
    }
}

// ====== K34: per (b,q): EL = J@Wl - mask, softmax over k, U = W@Ww (fp16 I/O) ======
__global__ void k34_softmax_U(const float* __restrict__ mask,
                              const float* __restrict__ Wl,
                              const float* __restrict__ Ww) {
    extern __shared__ float sE[];       // [1024][17]
    __shared__ float sWl[256];
    __shared__ float sWw[256];
    __shared__ float red[8][16];
    __shared__ float sInv[16];

    int q = blockIdx.x, b = blockIdx.y;
    int tid = threadIdx.x;
    sWl[tid] = Wl[tid & 255];
    sWw[tid] = Ww[tid & 255];
    __syncthreads();

    const __half* Jb = g_J + (size_t)b * 16777216 + (size_t)q * 1024;
    float psum[16] = {};

#pragma unroll
    for (int it = 0; it < 2; it++) {
        int k = it * 512 + tid * 2;
        float j0[16], j1[16];
#pragma unroll
        for (int h = 0; h < 16; h++) {
            __half2 jj = *(const __half2*)&Jb[(size_t)h * 1048576 + k];
            float2 f = __half22float2(jj);
            j0[h] = f.x; j1[h] = f.y;
        }
        float mk0 = mask[b * 1024 + k];
        float mk1 = mask[b * 1024 + k + 1];
#pragma unroll
        for (int g = 0; g < 16; g++) {
            float el0 = -mk0, el1 = -mk1;
#pragma unroll
            for (int h = 0; h < 16; h++) {
                float wl = sWl[h * 16 + g];
                el0 = fmaf(j0[h], wl, el0);
                el1 = fmaf(j1[h], wl, el1);
            }
            float e0 = fast_exp(el0);
            float e1 = fast_exp(el1);
            sE[k * 17 + g] = e0;
            sE[(k + 1) * 17 + g] = e1;
            psum[g] += e0 + e1;
        }
    }
#pragma unroll
    for (int g = 0; g < 16; g++) {
        float v = psum[g];
#pragma unroll
        for (int off = 16; off > 0; off >>= 1)
            v += __shfl_down_sync(0xffffffff, v, off);
        if ((tid & 31) == 0) red[tid >> 5][g] = v;
    }
    __syncthreads();
    if (tid < 16) {
        float tsum = 0.f;
#pragma unroll
        for (int w = 0; w < 8; w++) tsum += red[w][tid];
        sInv[tid] = USCALE / tsum;
    }
    __syncthreads();

    __half* Ub = g_U + (size_t)b * 16777216 + (size_t)q * 1024;
#pragma unroll
    for (int it = 0; it < 2; it++) {
        int k = it * 512 + tid * 2;
        float e0[16], e1[16];
#pragma unroll
        for (int g = 0; g < 16; g++) {
            e0[g] = sE[k * 17 + g] * sInv[g];
            e1[g] = sE[(k + 1) * 17 + g] * sInv[g];
        }
#pragma unroll
        for (int v = 0; v < 16; v++) {
            float u0 = 0.f, u1 = 0.f;
#pragma unroll
            for (int g = 0; g < 16; g++) {
                float ww = sWw[g * 16 + v];
                u0 = fmaf(e0[g], ww, u0);
                u1 = fmaf(e1[g], ww, u1);
            }
            *(__half2*)&Ub[(size_t)v * 1048576 + k] = __floats2half2_rn(u0, u1);
        }
    }
}

// ================= K5: O = U.V per (b,v), HMMA, 128x64, KC=64 DB =================
__global__ __launch_bounds__(256) void k5_O() {
    extern __shared__ __half sm5[];
    __half* Asb[2] = { sm5, sm5 + 128 * 72 };
    __half* Bsb[2] = { sm5 + 2 * 128 * 72, sm5 + 2 * 128 * 72 + 64 * 72 };
    int bv = blockIdx.y;
    int b = bv >> 4, v = bv & 15;
    int q0 = blockIdx.x * 128;
    const __half* U  = g_U + ((size_t)bv << 20);
    const __half* Vb = g_Vh + ((size_t)bv << 16);

    int t = threadIdx.x, lane = t & 31, warp = t >> 5;
    int alr = t >> 1, als = (t & 1) * 32;   // A: 4 uint4
    int blr = t >> 2, bls = (t & 3) * 16;   // B: 2 uint4

    {
        const uint4* as = (const uint4*)(U + (size_t)(q0 + alr) * 1024 + als);
        const uint4* bs = (const uint4*)(Vb + (blr << 6) + bls);
        uint4* ad = (uint4*)(Asb[0] + alr * 72 + als);
        uint4* bd = (uint4*)(Bsb[0] + blr * 72 + bls);
#pragma unroll
        for (int i = 0; i < 4; i++) ad[i] = as[i];
        bd[0] = bs[0]; bd[1] = bs[1];
    }
    __syncthreads();

    int wm = (warp >> 1) * 32, wn = (warp & 1) * 32;
    int amr = lane & 15, akc = (lane >> 4) * 8;                 // A normal
    int btr = (lane & 7) + ((lane & 8) ? 8 : 0);                // B trans: k row offset
    int btc = (lane & 16) ? 8 : 0;                              // B trans: n col offset

    float acc[2][4][4] = {};
    for (int ch = 0; ch < 16; ch++) {
        int buf = ch & 1;
        uint4 pa[4], pb[2];
        if (ch < 15) {
            int kn = (ch + 1) * 64;
            const uint4* as = (const uint4*)(U + (size_t)(q0 + alr) * 1024 + kn + als);
            const uint4* bs = (const uint4*)(Vb + ((kn + blr) << 6) + bls);
#pragma unroll
            for (int i = 0; i < 4; i++) pa[i] = as[i];
            pb[0] = bs[0]; pb[1] = bs[1];
        }
#pragma unroll
        for (int ks = 0; ks < 4; ks++) {
            int kk = ks * 16;
            uint32_t af[2][4], bf[2][4];
#pragma unroll
            for (int mi = 0; mi < 2; mi++)
                ldm4(af[mi], cvta_s(Asb[buf] + (wm + mi * 16 + amr) * 72 + kk + akc));
#pragma unroll
            for (int np = 0; np < 2; np++)
                ldm4t(bf[np], cvta_s(Bsb[buf] + (kk + btr) * 72 + wn + np * 16 + btc));
#pragma unroll
            for (int mi = 0; mi < 2; mi++)
#pragma unroll
                for (int ni = 0; ni < 4; ni++)
                    mma16816(acc[mi][ni], af[mi], &bf[ni >> 1][(ni & 1) * 2]);
        }
        if (ch < 15) {
            int nb = buf ^ 1;
            uint4* ad = (uint4*)(Asb[nb] + alr * 72 + als);
            uint4* bd = (uint4*)(Bsb[nb] + blr * 72 + bls);
#pragma unroll
            for (int i = 0; i < 4; i++) ad[i] = pa[i];
            bd[0] = pb[0]; bd[1] = pb[1];
        }
        __syncthreads();
    }

    int row = lane >> 2, colp = (lane & 3) * 2;
#pragma unroll
    for (int mi = 0; mi < 2; mi++) {
        int q = q0 + wm + mi * 16 + row;
#pragma unroll
        for (int ni = 0; ni < 4; ni++) {
            int d = wn + ni * 8 + colp;
            float* p = g_O + b * 1048576 + q * 1024 + v * 64 + d;
            *(float2*)p = make_float2(acc[mi][ni][0] * UINV, acc[mi][ni][1] * UINV);
            *(float2*)(p + 8 * 1024) = make_float2(acc[mi][ni][2] * UINV, acc[mi][ni][3] * UINV);
        }
    }
}

// ================= K6: partial C[c][q] = sum_j Wo'[j][c] * O[q][j], split-K=2 ====
__global__ __launch_bounds__(256) void k6_part(const float* __restrict__ Wo) {
    __shared__ float As[2][8][128];
    __shared__ float Bs[2][8 * 132];
    int z = blockIdx.z;
    int b = z >> 1, ks = z & 1;
    int c0 = blockIdx.x * 128, q0 = blockIdx.y * 128;
    int jb = ks * 512;
    const float* Ob = g_O + b * 1048576;

    int t = threadIdx.x;
    int lk = t >> 5, lc = (t & 31) * 4;
    int nq = t >> 1, j4 = (t & 1) * 4;
    int ty = t >> 4, tx = t & 15;

    int j = jb + lk;
    int wrow = ((j & 63) << 4) | (j >> 6);
    float4 a = *(const float4*)&Wo[wrow * 512 + c0 + lc];
    float4 o = *(const float4*)&Ob[(q0 + nq) * 1024 + jb + j4];
    *(float4*)&As[0][lk][lc] = a;
    Bs[0][(j4 + 0) * 132 + nq] = o.x; Bs[0][(j4 + 1) * 132 + nq] = o.y;
    Bs[0][(j4 + 2) * 132 + nq] = o.z; Bs[0][(j4 + 3) * 132 + nq] = o.w;
    __syncthreads();

    float acc[8][8] = {};
    for (int ct = 0; ct < 64; ct++) {
        int buf = ct & 1;
        if (ct < 63) {
            j = jb + (ct + 1) * 8 + lk;
            wrow = ((j & 63) << 4) | (j >> 6);
            a = *(const float4*)&Wo[wrow * 512 + c0 + lc];
            o = *(const float4*)&Ob[(q0 + nq) * 1024 + jb + (ct + 1) * 8 + j4];
        }
#pragma unroll
        for (int kk = 0; kk < 8; kk++) {
            float ar[8], br[8];
            *(float4*)&ar[0] = *(const float4*)&As[buf][kk][ty * 8];
            *(float4*)&ar[4] = *(const float4*)&As[buf][kk][ty * 8 + 4];
            *(float4*)&br[0] = *(const float4*)&Bs[buf][kk * 132 + tx * 8];
            *(float4*)&br[4] = *(const float4*)&Bs[buf][kk * 132 + tx * 8 + 4];
#pragma unroll
            for (int i = 0; i < 8; i++)
#pragma unroll
                for (int jj = 0; jj < 8; jj++)
                    acc[i][jj] = fmaf(ar[i], br[jj], acc[i][jj]);
        }
        if (ct < 63) {
            int nb = buf ^ 1;
            *(float4*)&As[nb][lk][lc] = a;
            Bs[nb][(j4 + 0) * 132 + nq] = o.x; Bs[nb][(j4 + 1) * 132 + nq] = o.y;
            Bs[nb][(j4 + 2) * 132 + nq] = o.z; Bs[nb][(j4 + 3) * 132 + nq] = o.w;
        }
        __syncthreads();
    }
    float* Pp = g_P + (size_t)z * 524288;
#pragma unroll
    for (int i = 0; i < 8; i++) {
        size_t row = (size_t)(c0 + ty * 8 + i) * 1024 + q0 + tx * 8;
        *(float4*)&Pp[row]     = make_float4(acc[i][0], acc[i][1], acc[i][2], acc[i][3]);
        *(float4*)&Pp[row + 4] = make_float4(acc[i][4], acc[i][5], acc[i][6], acc[i][7]);
    }
}

// ================= K7: out = inp + P0 + P1 =================
__global__ void k7_combine(const float* __restrict__ inp, float* __restrict__ out) {
    int gid = blockIdx.x * 256 + threadIdx.x;
    size_t fl = (size_t)gid * 4;
    int b = (int)(fl >> 19);
    size_t loc = fl & 524287;
    float4 iv = *(const float4*)(inp + fl);
    float4 p0 = *(const float4*)(g_P + (size_t)b * 1048576 + loc);
    float4 p1 = *(const float4*)(g_P + (size_t)b * 1048576 + 524288 + loc);
    *(float4*)(out + fl) = make_float4(iv.x + p0.x + p1.x, iv.y + p0.y + p1.y,
                                       iv.z + p0.z + p1.z, iv.w + p0.w + p1.w);
}

// ================= launch =================
extern "C" void kernel_launch(void* const* d_in, const int* in_sizes, int n_in,
                              void* d_out, int out_size) {
    const float* inp  = (const float*)d_in[0];
    const float* mask = (const float*)d_in[1];
    const float* Wq   = (const float*)d_in[2];
    const float* Wk   = (const float*)d_in[3];
    const float* Wv   = (const float*)d_in[4];
    const float* aq   = (const float*)d_in[5];
    const float* ak   = (const float*)d_in[6];
    const float* av   = (const float*)d_in[7];
    const float* Wl   = (const float*)d_in[8];
    const float* Ww   = (const float*)d_in[9];
    const float* Wo   = (const float*)d_in[10];
    float* out = (float*)d_out;

    const int SMEM_K34 = 1024 * 17 * 4;                       // 69632
    const int SMEM_K5  = (2 * 128 * 72 + 2 * 64 * 72) * 2;    // 55296
    cudaFuncSetAttribute(k34_softmax_U, cudaFuncAttributeMaxDynamicSharedMemorySize, SMEM_K34);
    cudaFuncSetAttribute(k5_O, cudaFuncAttributeMaxDynamicSharedMemorySize, SMEM_K5);

    kc0<<<5120, 256>>>(inp, Wq, Wk, Wv, aq, ak, av);
    k1_proj<<<dim3(8, 8, 6), 256>>>();
    k2_J<<<dim3(8, 8, 32), 256>>>();
    k34_softmax_U<<<dim3(1024, 2), 256, SMEM_K34>>>(mask, Wl, Ww);
    k5_O<<<dim3(8, 32), 256, SMEM_K5>>>();
    k6_part<<<dim3(4, 8, 4), 256>>>(Wo);
    k7_combine<<<1024, 256>>>(inp, out);
}

// round 5
// speedup vs baseline: 4.5238x; 1.6553x over previous
#include <cuda_runtime.h>
#include <cuda_fp16.h>
#include <cstdint>

#define CIN 512
#define SEQ 1024

// ---------------- scratch ----------------
__device__ __half g_inp16[2 * 512 * 1024];           // [b][c][s]
__device__ __half g_W16[3 * 512 * 1024];             // [w][c][h*64+d] scale-folded
__device__ __half g_Wo16[1024 * 512];                // [j'=v*64+d][c] permuted fp16 Wo
__device__ __half g_Qh[2 * 16 * 1024 * 64];          // [b][h][s][d]
__device__ __half g_Kh[2 * 16 * 1024 * 64];          // [b][h][s][d]
__device__ __half g_Vh[2 * 16 * 1024 * 64];          // [b][h][k][d]
__device__ __half g_J[(size_t)2 * 16 * 1024 * 1024]; // [b][h][q][k] 64 MB
__device__ __half g_U[(size_t)2 * 16 * 1024 * 1024]; // [b][v][q][k] 64 MB (x256)
__device__ __half g_Oh[2 * 1024 * 1024];             // [b][q][v*64+d] fp16

#define USCALE 256.0f
#define UINV   (1.0f / 256.0f)

// ---------------- fast exp on the FMA pipe ----------------
__device__ __forceinline__ float fast_exp(float x) {
    float t  = fmaf(x, 1.4426950408889634f, 12582912.0f);
    float fi = t - 12582912.0f;
    float f  = fmaf(x, 1.4426950408889634f, -fi);
    int   n  = __float_as_int(t) - 0x4B400000;
    float p  = 1.33335581e-3f;
    p = fmaf(p, f, 9.61812911e-3f);
    p = fmaf(p, f, 5.55041087e-2f);
    p = fmaf(p, f, 2.40226507e-1f);
    p = fmaf(p, f, 6.93147181e-1f);
    p = fmaf(p, f, 1.0f);
    return p * __int_as_float((n + 127) << 23);
}

// ---------------- mma helpers ----------------
__device__ __forceinline__ uint32_t cvta_s(const void* p) {
    return (uint32_t)__cvta_generic_to_shared(p);
}
__device__ __forceinline__ void ldm4(uint32_t* r, uint32_t a) {
    asm volatile("ldmatrix.sync.aligned.m8n8.x4.shared.b16 {%0,%1,%2,%3}, [%4];"
        : "=r"(r[0]), "=r"(r[1]), "=r"(r[2]), "=r"(r[3]) : "r"(a));
}
__device__ __forceinline__ void ldm4t(uint32_t* r, uint32_t a) {
    asm volatile("ldmatrix.sync.aligned.m8n8.x4.trans.shared.b16 {%0,%1,%2,%3}, [%4];"
        : "=r"(r[0]), "=r"(r[1]), "=r"(r[2]), "=r"(r[3]) : "r"(a));
}
__device__ __forceinline__ void mma16816(float* c, const uint32_t* a, const uint32_t* b) {
    asm volatile("mma.sync.aligned.m16n8k16.row.col.f32.f16.f16.f32 "
        "{%0,%1,%2,%3}, {%4,%5,%6,%7}, {%8,%9}, {%0,%1,%2,%3};"
        : "+f"(c[0]), "+f"(c[1]), "+f"(c[2]), "+f"(c[3])
        : "r"(a[0]), "r"(a[1]), "r"(a[2]), "r"(a[3]), "r"(b[0]), "r"(b[1]));
}

// ================= KC0: fp16 conversions + weight reorders =================
__global__ __launch_bounds__(256) void kc0(const float* __restrict__ inp,
        const float* __restrict__ Wq, const float* __restrict__ Wk,
        const float* __restrict__ Wv,
        const float* __restrict__ aq, const float* __restrict__ ak,
        const float* __restrict__ av, const float* __restrict__ Wo) {
    int t = blockIdx.x * 256 + threadIdx.x;
    if (t < 524288) {
        float2 v = *(const float2*)(inp + (size_t)t * 2);
        *(__half2*)(g_inp16 + (size_t)t * 2) = __floats2half2_rn(v.x, v.y);
    }
    int u = t - 524288;
    if (u >= 0 && u < 3 * 262144) {
        int w = u / 262144, o = u % 262144;
        int c = o >> 9, jp = (o & 511) * 2;       // j' = h*64+d, d even
        int h = jp >> 6, d = jp & 63;
        const float* W = (w == 0) ? Wq : ((w == 1) ? Wk : Wv);
        float al = (w == 0) ? aq[0] : ((w == 1) ? ak[0] : av[0]);
        float sc = 1.0f / (1.0f + fast_exp(-al));
        float x0 = W[c * 1024 + d * 16 + h] * sc;
        float x1 = W[c * 1024 + (d + 1) * 16 + h] * sc;
        *(__half2*)(g_W16 + w * 524288 + c * 1024 + jp) = __floats2half2_rn(x0, x1);
    }
    int u2 = t - 1310720;
    if (u2 >= 0 && u2 < 262144) {
        int jp = u2 >> 8, cp = (u2 & 255) * 2;    // j' = v*64+d
        int wrow = ((jp & 63) << 4) | (jp >> 6);  // real row d*16+v
        *(__half2*)(g_Wo16 + jp * 512 + cp) =
            __floats2half2_rn(Wo[wrow * 512 + cp], Wo[wrow * 512 + cp + 1]);
    }
}

// ================= K1: QKV projection, HMMA, 128x128, KC=32 DB =================
__global__ __launch_bounds__(256) void k1_proj() {
    __shared__ __half As[2][32 * 136];   // [k=c][m=s]
    __shared__ __half Bs[2][32 * 136];   // [k=c][n=j']
    int z = blockIdx.z;
    int b = z / 3, w = z % 3;
    int n0 = blockIdx.x * 128, m0 = blockIdx.y * 128;
    const __half* Ag = g_inp16 + b * 524288;
    const __half* Bg = g_W16 + w * 524288;

    int t = threadIdx.x, lane = t & 31, warp = t >> 5;
    int lrow = t >> 3, lcol = (t & 7) * 16;

    {
        const uint4* as = (const uint4*)(Ag + lrow * 1024 + m0 + lcol);
        const uint4* bs = (const uint4*)(Bg + lrow * 1024 + n0 + lcol);
        uint4* ad = (uint4*)(As[0] + lrow * 136 + lcol);
        uint4* bd = (uint4*)(Bs[0] + lrow * 136 + lcol);
        ad[0] = as[0]; ad[1] = as[1];
        bd[0] = bs[0]; bd[1] = bs[1];
    }
    __syncthreads();

    int wm = (warp >> 2) * 64, wn = (warp & 3) * 32;
    int a_r = (lane & 7) + ((lane & 16) ? 8 : 0);
    int a_c = (lane & 8) ? 8 : 0;
    int b_r = (lane & 7) + ((lane & 8) ? 8 : 0);
    int b_c = (lane & 16) ? 8 : 0;

    float acc[4][4][4] = {};
    for (int ch = 0; ch < 16; ch++) {
        int buf = ch & 1;
        uint4 pa0, pa1, pb0, pb1;
        if (ch < 15) {
            const uint4* as = (const uint4*)(Ag + ((ch + 1) * 32 + lrow) * 1024 + m0 + lcol);
            const uint4* bs = (const uint4*)(Bg + ((ch + 1) * 32 + lrow) * 1024 + n0 + lcol);
            pa0 = as[0]; pa1 = as[1];
            pb0 = bs[0]; pb1 = bs[1];
        }
#pragma unroll
        for (int ks = 0; ks < 2; ks++) {
            int kk = ks * 16;
            uint32_t af[4][4], bf[2][4];
#pragma unroll
            for (int mi = 0; mi < 4; mi++)
                ldm4t(af[mi], cvta_s(As[buf] + (kk + a_r) * 136 + wm + mi * 16 + a_c));
#pragma unroll
            for (int np = 0; np < 2; np++)
                ldm4t(bf[np], cvta_s(Bs[buf] + (kk + b_r) * 136 + wn + np * 16 + b_c));
#pragma unroll
            for (int mi = 0; mi < 4; mi++)
#pragma unroll
                for (int ni = 0; ni < 4; ni++)
                    mma16816(acc[mi][ni], af[mi], &bf[ni >> 1][(ni & 1) * 2]);
        }
        if (ch < 15) {
            int nb = buf ^ 1;
            uint4* ad = (uint4*)(As[nb] + lrow * 136 + lcol);
            uint4* bd = (uint4*)(Bs[nb] + lrow * 136 + lcol);
            ad[0] = pa0; ad[1] = pa1;
            bd[0] = pb0; bd[1] = pb1;
        }
        __syncthreads();
    }

    __half* base = (w == 0) ? g_Qh : ((w == 1) ? g_Kh : g_Vh);
    int row = lane >> 2, colp = (lane & 3) * 2;
#pragma unroll
    for (int mi = 0; mi < 4; mi++) {
        int s = m0 + wm + mi * 16 + row;
#pragma unroll
        for (int ni = 0; ni < 4; ni++) {
            int jp = n0 + wn + ni * 8 + colp;
            int h = jp >> 6, d = jp & 63;
            __half* p = base + (((b * 16 + h) * 1024 + s) << 6) + d;
            *(__half2*)p = __floats2half2_rn(acc[mi][ni][0], acc[mi][ni][1]);
            *(__half2*)(p + (8 << 6)) = __floats2half2_rn(acc[mi][ni][2], acc[mi][ni][3]);
        }
    }
}

// ================= K2: J = Q.K^T per (b,h), HMMA, 128x128, K=64 single-shot =========
__global__ __launch_bounds__(256) void k2_J() {
    __shared__ __half As[128 * 72];  // [q][d]
    __shared__ __half Bs[128 * 72];  // [k'][d]
    int bh = blockIdx.z;
    int q0 = blockIdx.y * 128, k0 = blockIdx.x * 128;
    const __half* Qb = g_Qh + ((size_t)bh << 16);
    const __half* Kb = g_Kh + ((size_t)bh << 16);

    int t = threadIdx.x, lane = t & 31, warp = t >> 5;
    {
        int lr = t >> 1, ls = (t & 1) * 32;
        const uint4* qs = (const uint4*)(Qb + ((q0 + lr) << 6) + ls);
        const uint4* ks = (const uint4*)(Kb + ((k0 + lr) << 6) + ls);
        uint4* ad = (uint4*)(As + lr * 72 + ls);
        uint4* bd = (uint4*)(Bs + lr * 72 + ls);
#pragma unroll
        for (int i = 0; i < 4; i++) { ad[i] = qs[i]; bd[i] = ks[i]; }
    }
    __syncthreads();

    int wm = (warp >> 2) * 64, wn = (warp & 3) * 32;
    int amr = lane & 15, akc = (lane >> 4) * 8;
    int bnr = (lane & 7) + ((lane & 16) ? 8 : 0);
    int bkc = (lane & 8) ? 8 : 0;

    float acc[4][4][4] = {};
#pragma unroll
    for (int ks = 0; ks < 4; ks++) {
        int kk = ks * 16;
        uint32_t af[4][4], bf[2][4];
#pragma unroll
        for (int mi = 0; mi < 4; mi++)
            ldm4(af[mi], cvta_s(As + (wm + mi * 16 + amr) * 72 + kk + akc));
#pragma unroll
        for (int np = 0; np < 2; np++)
            ldm4(bf[np], cvta_s(Bs + (wn + np * 16 + bnr) * 72 + kk + bkc));
#pragma unroll
        for (int mi = 0; mi < 4; mi++)
#pragma unroll
            for (int ni = 0; ni < 4; ni++)
                mma16816(acc[mi][ni], af[mi], &bf[ni >> 1][(ni & 1) * 2]);
    }

    __half* Jp = g_J + ((size_t)bh << 20);
    int row = lane >> 2, colp = (lane & 3) * 2;
#pragma unroll
    for (int mi = 0; mi < 4; mi++) {
        int q = q0 + wm + mi * 16 + row;
#pragma unroll
        for (int ni = 0; ni < 4; ni++) {
            int kc = k0 + wn + ni * 8 + colp;
            *(__half2*)&Jp[(size_t)q * 1024 + kc] =
                __floats2half2_rn(acc[mi][ni][0], acc[mi][ni][1]);
            *(__half2*)&Jp[(size_t)(q + 8) * 1024 + kc] =
                __floats2half2_rn(acc[mi][ni][2], acc[mi][ni][3]);
        }
    }
}

// ====== K34: per (b,q): EL = J@Wl - mask, softmax over k, U = W@Ww — all HMMA ======
// smem sJ[h][1032] holds J; exp values overwrite consumed 16x16 regions in place.
#define JST 1032
__global__ __launch_bounds__(256) void k34_softmax_U(const float* __restrict__ mask,
                                                     const float* __restrict__ Wl,
                                                     const float* __restrict__ Ww) {
    extern __shared__ __half sJ[];          // [16][JST] halves (33 KB)
    __shared__ __half sWl[16 * 24];         // Wl [h][g]
    __shared__ __half sWwS[16 * 24];        // Ww'^T [v][g] = inv[g]*Ww[g][v]
    __shared__ float sMask[1024];
    __shared__ float red[8][16];
    __shared__ float sInv[16];

    int q = blockIdx.x, b = blockIdx.y;
    int tid = threadIdx.x, lane = tid & 31, w = tid >> 5;
    const __half* Jb = g_J + (size_t)b * 16777216 + (size_t)q * 1024;

    { int h = tid >> 4, g = tid & 15; sWl[h * 24 + g] = __float2half(Wl[h * 16 + g]); }
    { float4 m4 = *(const float4*)(mask + b * 1024 + tid * 4);
      *(float4*)&sMask[tid * 4] = m4; }
    // load J: warp w loads planes 2w, 2w+1 (coalesced uint4)
#pragma unroll
    for (int p = 0; p < 2; p++) {
        int h = w * 2 + p;
        const uint4* src = (const uint4*)(Jb + (size_t)h * 1048576);
#pragma unroll
        for (int it = 0; it < 4; it++)
            *(uint4*)&sJ[h * JST + (lane + it * 32) * 8] = src[lane + it * 32];
    }
    __syncthreads();

    // ---- phase 1: EL tiles + exp (A = J via ldm4t [h][kpos], B = Wl via ldm4t) ----
    uint32_t bWl[4];
    {
        int b_r = (lane & 7) + ((lane & 8) ? 8 : 0);
        int b_c = (lane & 16) ? 8 : 0;
        ldm4t(bWl, cvta_s(sWl + b_r * 24 + b_c));
    }
    int a_r = (lane & 7) + ((lane & 16) ? 8 : 0);
    int a_c = (lane & 8) ? 8 : 0;
    int r = lane >> 2, cg = (lane & 3) * 2;
    int kbase = w * 128;
    float psum4[4] = {};
#pragma unroll
    for (int i = 0; i < 8; i++) {
        int kcol = kbase + i * 16;
        uint32_t af[4];
        ldm4t(af, cvta_s(sJ + a_r * JST + kcol + a_c));
        float c0[4] = {}, c1[4] = {};
        mma16816(c0, af, &bWl[0]);   // g 0-7
        mma16816(c1, af, &bWl[2]);   // g 8-15
        float mk0 = sMask[kcol + r], mk1 = sMask[kcol + r + 8];
        float e00 = fast_exp(c0[0] - mk0), e01 = fast_exp(c0[1] - mk0);
        float e02 = fast_exp(c0[2] - mk1), e03 = fast_exp(c0[3] - mk1);
        float e10 = fast_exp(c1[0] - mk0), e11 = fast_exp(c1[1] - mk0);
        float e12 = fast_exp(c1[2] - mk1), e13 = fast_exp(c1[3] - mk1);
        psum4[0] += e00 + e02; psum4[1] += e01 + e03;
        psum4[2] += e10 + e12; psum4[3] += e11 + e13;
        // overlay store: tile element (kp_local, g) at sJ[kp_local*JST + kcol + g]
        *(__half2*)&sJ[r * JST + kcol + cg]           = __floats2half2_rn(e00, e01);
        *(__half2*)&sJ[(r + 8) * JST + kcol + cg]     = __floats2half2_rn(e02, e03);
        *(__half2*)&sJ[r * JST + kcol + 8 + cg]       = __floats2half2_rn(e10, e11);
        *(__half2*)&sJ[(r + 8) * JST + kcol + 8 + cg] = __floats2half2_rn(e12, e13);
    }
    // reduce over lanes sharing the same g set (lane & 3)
#pragma unroll
    for (int s = 16; s >= 4; s >>= 1) {
#pragma unroll
        for (int j = 0; j < 4; j++)
            psum4[j] += __shfl_xor_sync(0xffffffffu, psum4[j], s);
    }
    if (lane < 4) {
        red[w][2 * lane]     = psum4[0];
        red[w][2 * lane + 1] = psum4[1];
        red[w][2 * lane + 8] = psum4[2];
        red[w][2 * lane + 9] = psum4[3];
    }
    __syncthreads();
    if (tid < 16) {
        float s = 0.f;
#pragma unroll
        for (int ww = 0; ww < 8; ww++) s += red[ww][tid];
        sInv[tid] = USCALE / s;
    }
    __syncthreads();
    { int v = tid >> 4, g = tid & 15;
      sWwS[v * 24 + g] = __float2half(sInv[g] * Ww[g * 16 + v]); }
    __syncthreads();

    // ---- phase 2: U^T[v][kpos] = WwS^T @ W^T  (A = WwS^T ldm4, B = e tile ldm4) ----
    uint32_t aW[4];
    { int amr = lane & 15, akc = (lane >> 4) * 8;
      ldm4(aW, cvta_s(sWwS + amr * 24 + akc)); }
    int bnr = (lane & 7) + ((lane & 16) ? 8 : 0);
    int bkc = (lane & 8) ? 8 : 0;
    __half* Ub = g_U + (size_t)b * 16777216 + (size_t)q * 1024;
#pragma unroll
    for (int i = 0; i < 8; i++) {
        int kcol = kbase + i * 16;
        uint32_t bf[4];
        ldm4(bf, cvta_s(sJ + bnr * JST + kcol + bkc));
        float c0[4] = {}, c1[4] = {};
        mma16816(c0, aW, &bf[0]);   // kpos 0-7
        mma16816(c1, aW, &bf[2]);   // kpos 8-15
        *(__half2*)&Ub[(size_t)r * 1048576 + kcol + cg] =
            __floats2half2_rn(c0[0], c0[1]);
        *(__half2*)&Ub[(size_t)(r + 8) * 1048576 + kcol + cg] =
            __floats2half2_rn(c0[2], c0[3]);
        *(__half2*)&Ub[(size_t)r * 1048576 + kcol + 8 + cg] =
            __floats2half2_rn(c1[0], c1[1]);
        *(__half2*)&Ub[(size_t)(r + 8) * 1048576 + kcol + 8 + cg] =
            __floats2half2_rn(c1[2], c1[3]);
    }
}

// ================= K5: O = U.V per (b,v), HMMA, 128x64, KC=64 DB, fp16 out =========
__global__ __launch_bounds__(256) void k5_O() {
    extern __shared__ __half sm5[];
    __half* Asb[2] = { sm5, sm5 + 128 * 72 };
    __half* Bsb[2] = { sm5 + 2 * 128 * 72, sm5 + 2 * 128 * 72 + 64 * 72 };
    int bv = blockIdx.y;
    int b = bv >> 4, v = bv & 15;
    int q0 = blockIdx.x * 128;
    const __half* U  = g_U + ((size_t)bv << 20);
    const __half* Vb = g_Vh + ((size_t)bv << 16);

    int t = threadIdx.x, lane = t & 31, warp = t >> 5;
    int alr = t >> 1, als = (t & 1) * 32;
    int blr = t >> 2, bls = (t & 3) * 16;

    {
        const uint4* as = (const uint4*)(U + (size_t)(q0 + alr) * 1024 + als);
        const uint4* bs = (const uint4*)(Vb + (blr << 6) + bls);
        uint4* ad = (uint4*)(Asb[0] + alr * 72 + als);
        uint4* bd = (uint4*)(Bsb[0] + blr * 72 + bls);
#pragma unroll
        for (int i = 0; i < 4; i++) ad[i] = as[i];
        bd[0] = bs[0]; bd[1] = bs[1];
    }
    __syncthreads();

    int wm = (warp >> 1) * 32, wn = (warp & 1) * 32;
    int amr = lane & 15, akc = (lane >> 4) * 8;
    int btr = (lane & 7) + ((lane & 8) ? 8 : 0);
    int btc = (lane & 16) ? 8 : 0;

    float acc[2][4][4] = {};
    for (int ch = 0; ch < 16; ch++) {
        int buf = ch & 1;
        uint4 pa[4], pb[2];
        if (ch < 15) {
            int kn = (ch + 1) * 64;
            const uint4* as = (const uint4*)(U + (size_t)(q0 + alr) * 1024 + kn + als);
            const uint4* bs = (const uint4*)(Vb + ((kn + blr) << 6) + bls);
#pragma unroll
            for (int i = 0; i < 4; i++) pa[i] = as[i];
            pb[0] = bs[0]; pb[1] = bs[1];
        }
#pragma unroll
        for (int ks = 0; ks < 4; ks++) {
            int kk = ks * 16;
            uint32_t af[2][4], bf[2][4];
#pragma unroll
            for (int mi = 0; mi < 2; mi++)
                ldm4(af[mi], cvta_s(Asb[buf] + (wm + mi * 16 + amr) * 72 + kk + akc));
#pragma unroll
            for (int np = 0; np < 2; np++)
                ldm4t(bf[np], cvta_s(Bsb[buf] + (kk + btr) * 72 + wn + np * 16 + btc));
#pragma unroll
            for (int mi = 0; mi < 2; mi++)
#pragma unroll
                for (int ni = 0; ni < 4; ni++)
                    mma16816(acc[mi][ni], af[mi], &bf[ni >> 1][(ni & 1) * 2]);
        }
        if (ch < 15) {
            int nb = buf ^ 1;
            uint4* ad = (uint4*)(Asb[nb] + alr * 72 + als);
            uint4* bd = (uint4*)(Bsb[nb] + blr * 72 + bls);
#pragma unroll
            for (int i = 0; i < 4; i++) ad[i] = pa[i];
            bd[0] = pb[0]; bd[1] = pb[1];
        }
        __syncthreads();
    }

    int row = lane >> 2, colp = (lane & 3) * 2;
#pragma unroll
    for (int mi = 0; mi < 2; mi++) {
        int q = q0 + wm + mi * 16 + row;
#pragma unroll
        for (int ni = 0; ni < 4; ni++) {
            int d = wn + ni * 8 + colp;
            __half* p = g_Oh + b * 1048576 + q * 1024 + v * 64 + d;
            *(__half2*)p = __floats2half2_rn(acc[mi][ni][0] * UINV, acc[mi][ni][1] * UINV);
            *(__half2*)(p + 8 * 1024) =
                __floats2half2_rn(acc[mi][ni][2] * UINV, acc[mi][ni][3] * UINV);
        }
    }
}

// ================= K6: out[b,c,q] = inp + O @ Wo16, HMMA 64x128, KC=64 DB ==========
__global__ __launch_bounds__(256) void k6_out(const float* __restrict__ inp,
                                              float* __restrict__ out) {
    extern __shared__ __half sm6[];
    __half* Asb[2] = { sm6, sm6 + 64 * 72 };
    __half* Bsb[2] = { sm6 + 2 * 64 * 72, sm6 + 2 * 64 * 72 + 64 * 136 };
    float* Cs = (float*)sm6;   // reused after mainloop
    int b = blockIdx.z;
    int c0 = blockIdx.x * 128, q0 = blockIdx.y * 64;
    const __half* Oq = g_Oh + b * 1048576;

    int t = threadIdx.x, lane = t & 31, w = t >> 5;
    int alr = t >> 2, als = (t & 3) * 16;
    int blr = t >> 2, bls = (t & 3) * 32;

    {
        const uint4* as = (const uint4*)(Oq + (q0 + alr) * 1024 + als);
        uint4* ad = (uint4*)(Asb[0] + alr * 72 + als);
        ad[0] = as[0]; ad[1] = as[1];
        const uint4* bs = (const uint4*)(g_Wo16 + blr * 512 + c0 + bls);
        uint4* bd = (uint4*)(Bsb[0] + blr * 136 + bls);
        bd[0] = bs[0]; bd[1] = bs[1]; bd[2] = bs[2]; bd[3] = bs[3];
    }
    __syncthreads();

    int wm = (w >> 2) * 32, wn = (w & 3) * 32;
    int amr = lane & 15, akc = (lane >> 4) * 8;
    int b_r = (lane & 7) + ((lane & 8) ? 8 : 0);
    int b_c = (lane & 16) ? 8 : 0;

    float acc[2][4][4] = {};
    for (int ch = 0; ch < 16; ch++) {
        int buf = ch & 1;
        uint4 pa[2], pb[4];
        if (ch < 15) {
            int kn = (ch + 1) * 64;
            const uint4* as = (const uint4*)(Oq + (q0 + alr) * 1024 + kn + als);
            pa[0] = as[0]; pa[1] = as[1];
            const uint4* bs = (const uint4*)(g_Wo16 + (kn + blr) * 512 + c0 + bls);
            pb[0] = bs[0]; pb[1] = bs[1]; pb[2] = bs[2]; pb[3] = bs[3];
        }
#pragma unroll
        for (int ks = 0; ks < 4; ks++) {
            int kk = ks * 16;
            uint32_t af[2][4], bf[2][4];
#pragma unroll
            for (int mi = 0; mi < 2; mi++)
                ldm4(af[mi], cvta_s(Asb[buf] + (wm + mi * 16 + amr) * 72 + kk + akc));
#pragma unroll
            for (int np = 0; np < 2; np++)
                ldm4t(bf[np], cvta_s(Bsb[buf] + (kk + b_r) * 136 + wn + np * 16 + b_c));
#pragma unroll
            for (int mi = 0; mi < 2; mi++)
#pragma unroll
                for (int ni = 0; ni < 4; ni++)
                    mma16816(acc[mi][ni], af[mi], &bf[ni >> 1][(ni & 1) * 2]);
        }
        if (ch < 15) {
            int nb = buf ^ 1;
            uint4* ad = (uint4*)(Asb[nb] + alr * 72 + als);
            ad[0] = pa[0]; ad[1] = pa[1];
            uint4* bd = (uint4*)(Bsb[nb] + blr * 136 + bls);
            bd[0] = pb[0]; bd[1] = pb[1]; bd[2] = pb[2]; bd[3] = pb[3];
        }
        __syncthreads();
    }

    // transpose to Cs[c][q] (A/B smem dead now)
    int row = lane >> 2, cp = (lane & 3) * 2;
#pragma unroll
    for (int mi = 0; mi < 2; mi++)
#pragma unroll
        for (int ni = 0; ni < 4; ni++) {
            int qq = wm + mi * 16 + row;
            int cc2 = wn + ni * 8 + cp;
            Cs[cc2 * 68 + qq]           = acc[mi][ni][0];
            Cs[(cc2 + 1) * 68 + qq]     = acc[mi][ni][1];
            Cs[cc2 * 68 + qq + 8]       = acc[mi][ni][2];
            Cs[(cc2 + 1) * 68 + qq + 8] = acc[mi][ni][3];
        }
    __syncthreads();
#pragma unroll
    for (int i2 = 0; i2 < 8; i2++) {
        int idx = t + i2 * 256;
        int cc2 = idx >> 4, q4 = (idx & 15) * 4;
        size_t off = (size_t)b * 524288 + (size_t)(c0 + cc2) * 1024 + q0 + q4;
        float4 iv = *(const float4*)(inp + off);
        *(float4*)(out + off) = make_float4(iv.x + Cs[cc2 * 68 + q4],
                                            iv.y + Cs[cc2 * 68 + q4 + 1],
                                            iv.z + Cs[cc2 * 68 + q4 + 2],
                                            iv.w + Cs[cc2 * 68 + q4 + 3]);
    }
}

// ================= launch =================
extern "C" void kernel_launch(void* const* d_in, const int* in_sizes, int n_in,
                              void* d_out, int out_size) {
    const float* inp  = (const float*)d_in[0];
    const float* mask = (const float*)d_in[1];
    const float* Wq   = (const float*)d_in[2];
    const float* Wk   = (const float*)d_in[3];
    const float* Wv   = (const float*)d_in[4];
    const float* aq   = (const float*)d_in[5];
    const float* ak   = (const float*)d_in[6];
    const float* av   = (const float*)d_in[7];
    const float* Wl   = (const float*)d_in[8];
    const float* Ww   = (const float*)d_in[9];
    const float* Wo   = (const float*)d_in[10];
    float* out = (float*)d_out;

    const int SMEM_K34 = 16 * JST * 2;                        // 33024
    const int SMEM_K5  = (2 * 128 * 72 + 2 * 64 * 72) * 2;    // 55296
    const int SMEM_K6  = (2 * 64 * 72 + 2 * 64 * 136) * 2;    // 53248
    cudaFuncSetAttribute(k34_softmax_U, cudaFuncAttributeMaxDynamicSharedMemorySize, SMEM_K34);
    cudaFuncSetAttribute(k5_O, cudaFuncAttributeMaxDynamicSharedMemorySize, SMEM_K5);
    cudaFuncSetAttribute(k6_out, cudaFuncAttributeMaxDynamicSharedMemorySize, SMEM_K6);

    kc0<<<6144, 256>>>(inp, Wq, Wk, Wv, aq, ak, av, Wo);
    k1_proj<<<dim3(8, 8, 6), 256>>>();
    k2_J<<<dim3(8, 8, 32), 256>>>();
    k34_softmax_U<<<dim3(1024, 2), 256, SMEM_K34>>>(mask, Wl, Ww);
    k5_O<<<dim3(8, 32), 256, SMEM_K5>>>();
    k6_out<<<dim3(4, 16, 2), 256, SMEM_K6>>>(inp, out);
}